// round 12
// baseline (speedup 1.0000x reference)
#include <cuda_runtime.h>
#include <cuda_bf16.h>
#include <math.h>
#include <cstdint>

#define BATCH   64
#define DIMC    64
#define HEADS   8
#define DHEAD   64
#define INNER   512
#define MLPD    256
#define DEPTH   4
#define NPATCH  225
#define NTOK    226
#define M2      (2*BATCH*NTOK)   /* 28928 rows */
#define MBTOT   (M2/16)          /* 1808 m-blocks */
#define EPSV    1e-5f
#define SCALEV  0.125f

/* ---------------- mma helpers ---------------- */
__device__ __forceinline__ uint32_t smem_u32(const void* p) {
    uint32_t a;
    asm("{ .reg .u64 t; cvta.to.shared.u64 t, %1; cvt.u32.u64 %0, t; }" : "=r"(a) : "l"(p));
    return a;
}
__device__ __forceinline__ void mma_bf16(float* c, const uint32_t* a, const uint32_t* b) {
    asm volatile("mma.sync.aligned.m16n8k16.row.col.f32.bf16.bf16.f32 "
        "{%0,%1,%2,%3}, {%4,%5,%6,%7}, {%8,%9}, {%0,%1,%2,%3};"
        : "+f"(c[0]), "+f"(c[1]), "+f"(c[2]), "+f"(c[3])
        : "r"(a[0]), "r"(a[1]), "r"(a[2]), "r"(a[3]), "r"(b[0]), "r"(b[1]));
}
__device__ __forceinline__ void mma_tf32(float* c, const uint32_t* a, const uint32_t* b) {
    asm volatile("mma.sync.aligned.m16n8k8.row.col.f32.tf32.tf32.f32 "
        "{%0,%1,%2,%3}, {%4,%5,%6,%7}, {%8,%9}, {%0,%1,%2,%3};"
        : "+f"(c[0]), "+f"(c[1]), "+f"(c[2]), "+f"(c[3])
        : "r"(a[0]), "r"(a[1]), "r"(a[2]), "r"(a[3]), "r"(b[0]), "r"(b[1]));
}
__device__ __forceinline__ void ldm_x4_trans(uint32_t* r, uint32_t addr) {
    asm volatile("ldmatrix.sync.aligned.m8n8.x4.trans.shared.b16 {%0,%1,%2,%3}, [%4];"
        : "=r"(r[0]), "=r"(r[1]), "=r"(r[2]), "=r"(r[3]) : "r"(addr));
}
__device__ __forceinline__ uint32_t totf(float x) {
    uint32_t r; asm("cvt.rna.tf32.f32 %0, %1;" : "=r"(r) : "f"(x)); return r;
}
#define PACKBF(r, lo_, hi_) asm("cvt.rn.bf16x2.f32 %0, %1, %2;" : "=r"(r) : "f"(hi_), "f"(lo_))

/* fragment-layout word index (verified R5/R7) */
__host__ __device__ inline int faddr(int k, int n, int npairs) {
    return ((k>>3)*npairs + (n>>4))*128 + ((n&7)*4 + (k&3))*4 + (((n>>3)&1)*2) + ((k>>2)&1);
}
/* A-fragment word index in the global XNf buffer (m rows over MBTOT blocks) */
__device__ __forceinline__ uint32_t gword(int m, int k) {
    return (uint32_t)(((k>>3)*MBTOT + (m>>4))*128 + (m&7)*16 + ((m>>3)&1) + ((k>>2)&1)*2 + (k&3)*4);
}

/* ---------------- scratch ---------------- */
__device__ float    g_X  [(size_t)M2*DIMC];
__device__ uint32_t g_XNf[(size_t)M2*DIMC];   /* LN output, tf32 frag-order */
__device__ uint16_t g_Q [(size_t)M2*INNER];   /* bf16; attn writes O in-place */
__device__ uint16_t g_V [(size_t)M2*INNER];   /* bf16 */
__device__ uint16_t g_H [(size_t)M2*MLPD];    /* bf16 */
__device__ float    g_sdfm[BATCH*DIMC];
__device__ float    g_xmean[BATCH*2*DIMC];
__device__ uint32_t g_Wfrag[(size_t)DEPTH*131072];
#define OFF_QV   0
#define OFF_PROJ 65536
#define OFF_FF1  98304
#define OFF_FF2  114688

/* ---------------- prologue ---------------- */
__global__ void mean_kernel(const float* __restrict__ hsi, const float* __restrict__ lidar) {
    int idx = blockIdx.x*blockDim.x + threadIdx.x;
    if (idx >= BATCH*128) return;
    int b = idx >> 7, c = idx & 127;
    const float* src = (c < 64) ? (hsi + ((size_t)b*64 + c)*NPATCH)
                                : (lidar + ((size_t)b*64 + (c-64))*NPATCH);
    float s = 0.f;
    for (int p = 0; p < NPATCH; p++) s += src[p];
    g_xmean[idx] = s * (1.0f/NPATCH);
}

__global__ void dfm_kernel(const float* __restrict__ fmg_w) {
    int idx = blockIdx.x*blockDim.x + threadIdx.x;
    if (idx >= BATCH*64) return;
    int b = idx >> 6, d = idx & 63;
    const float* xm = g_xmean + b*128;
    const float* wc = fmg_w + d*65;
    float s = 0.f;
    for (int c = 0; c < 128; c++) s += xm[c] * wc[(size_t)c*4096];
    float sig = 1.0f/(1.0f + expf(-s));
    g_sdfm[idx] = sqrtf(sig * SCALEV);
}

__global__ void build_kernel(const float* __restrict__ hsi,
                             const float* __restrict__ cls_hsi, const float* __restrict__ cls_lidar,
                             const float* __restrict__ pos_hsi, const float* __restrict__ pos_lidar) {
    int idx = blockIdx.x*blockDim.x + threadIdx.x;
    if (idx >= M2*DIMC) return;
    int c  = idx & 63;
    int n  = (idx >> 6) % NTOK;
    int bp = idx / (NTOK*64);
    int b  = bp & 63;
    int br = bp >> 6;
    const float* cls = br ? cls_lidar : cls_hsi;
    const float* pos = br ? pos_lidar : pos_hsi;
    float v = (n == 0) ? cls[c] : hsi[((size_t)b*64 + c)*NPATCH + (n-1)];
    g_X[idx] = v + pos[n*64 + c];
}

/* ---------------- layernorm -> frag-order tf32 (phase start only) ---------------- */
__global__ void ln_frag_kernel(const float* __restrict__ Xp,
                               const float* __restrict__ g, const float* __restrict__ bb) {
    int w = threadIdx.x >> 5, lane = threadIdx.x & 31;
    int row = blockIdx.x*8 + w;
    const float* xr = Xp + (size_t)row*64;
    float x0 = xr[lane], x1 = xr[lane+32];
    float s = x0 + x1;
    #pragma unroll
    for (int o = 16; o; o >>= 1) s += __shfl_xor_sync(0xffffffffu, s, o);
    float m = s * (1.0f/64.0f);
    float d0 = x0 - m, d1 = x1 - m;
    float v = d0*d0 + d1*d1;
    #pragma unroll
    for (int o = 16; o; o >>= 1) v += __shfl_xor_sync(0xffffffffu, v, o);
    float r = rsqrtf(v*(1.0f/64.0f) + EPSV);
    g_XNf[gword(row, lane)]      = totf(d0*r*g[lane]    + bb[lane]);
    g_XNf[gword(row, lane+32)]   = totf(d1*r*g[lane+32] + bb[lane+32]);
}

/* ---------------- weight prep (fp32 -> tf32 frag layout) ---------------- */
__global__ void prep_qv(const float* __restrict__ qkv_w) {
    int idx = blockIdx.x*blockDim.x + threadIdx.x;
    if (idx >= DEPTH*64*1024) return;
    int n = idx & 1023, k = (idx >> 10) & 63, L = idx >> 16;
    float v = qkv_w[(size_t)L*64*1536 + k*1536 + (n < 512 ? n : n + 512)];
    g_Wfrag[(size_t)L*131072 + OFF_QV + faddr(k, n, 64)] = totf(v);
}
__global__ void prep_gen(const float* __restrict__ w, int K, int N, int dstoff, int total) {
    int idx = blockIdx.x*blockDim.x + threadIdx.x;
    if (idx >= total) return;
    int kn = K*N;
    int L = idx / kn, rem = idx % kn;
    int k = rem / N, n = rem % N;
    g_Wfrag[(size_t)L*131072 + dstoff + faddr(k, n, N >> 4)] = totf(w[(size_t)idx]);
}

/* ---------------- tf32 mma GEMM v4 ----------------
   AIN: 1 = bf16 A (shift to tf32), 2 = frag-order tf32 A (bulk copy, no cvt).
   OUT: 0 = fp32 C (ACC supported), 1 = bf16 C.
   QV_: dual-output Q/V with sd-scaling folded into Q.
   LNOUT: fused residual+LayerNorm epilogue -> writes g_XNf (needs OUT==0, BN==64==ldc). */
template<int BM, int BN, bool GELU_, bool ACC_, bool BIAS_, bool QV_, int AIN, int OUT, bool LNOUT>
__global__ void __launch_bounds__(256) tgemm(
    const void* __restrict__ Ap, const uint32_t* __restrict__ Bf,
    const float* __restrict__ bias, void* __restrict__ Cp_, void* __restrict__ C2p_,
    const float* __restrict__ lngamma, const float* __restrict__ lnbeta,
    int K, int lda, int Ntot, int ldc)
{
    constexpr int MBLKS = BM/16;
    constexpr int NPB   = BN/16;
    constexpr int MF    = BM/64;
    constexpr int WN    = BN/2;
    constexpr int NF    = WN/8;
    const int NPAIRS = Ntot >> 4;

    extern __shared__ uint32_t dsm[];
    uint32_t* Asm = dsm;                    /* 8*MBLKS*128 words */
    uint32_t* Bsm = dsm + 8*MBLKS*128;      /* 8*NPB*128 words */

    int t = threadIdx.x, lane = t & 31, w = t >> 5;
    int wm = w & 3, wn = w >> 2;
    int m0 = blockIdx.y * BM;
    int n0 = blockIdx.x * BN;
    int np0 = n0 >> 4;

    float acc[MF][NF][4];
    #pragma unroll
    for (int i = 0; i < MF; i++)
        #pragma unroll
        for (int j = 0; j < NF; j++)
            #pragma unroll
            for (int q = 0; q < 4; q++) acc[i][j][q] = 0.f;

    for (int kt = 0; kt < K; kt += 64) {
        /* ---- stage A ---- */
        if (AIN == 1) {
            #pragma unroll
            for (int it = 0; it < BM/32; it++) {
                int idx = t + it*256;
                int m = idx >> 3, k8 = (idx & 7)*8;
                uint4 v = *(const uint4*)((const uint16_t*)Ap + (size_t)(m0+m)*lda + kt + k8);
                const uint16_t* hp = (const uint16_t*)&v;
                int base = ((k8>>3)*MBLKS + (m>>4))*128 + (m&7)*16 + ((m>>3)&1);
                #pragma unroll
                for (int j = 0; j < 8; j++)
                    Asm[base + (j>>2)*2 + (j&3)*4] = ((uint32_t)hp[j]) << 16;
            }
        } else { /* AIN==2: bulk copy from frag-order global */
            const uint4* Afr = (const uint4*)Ap;
            int mb0 = m0 >> 4;
            #pragma unroll
            for (int it = 0; it < MBLKS; it++) {
                int i = t + it*256;
                int kc = i / (MBLKS*32);
                int rem = i % (MBLKS*32);
                ((uint4*)Asm)[i] = __ldg(Afr + (size_t)(kc*MBTOT + mb0 + (rem>>5))*32 + (rem&31));
            }
        }
        /* ---- stage B: bulk copy ---- */
        int kc0 = kt >> 3;
        #pragma unroll
        for (int it = 0; it < NPB; it++) {
            int i = t + it*256;
            int kc = i / (NPB*32);
            int rem = i % (NPB*32);
            int np = rem >> 5, l4 = rem & 31;
            ((uint4*)Bsm)[i] = __ldg((const uint4*)(Bf + (size_t)((kc0+kc)*NPAIRS + np0 + np)*128 + l4*4));
        }
        __syncthreads();

        #pragma unroll
        for (int kc = 0; kc < 8; kc++) {
            uint32_t af[MF][4];
            #pragma unroll
            for (int mf = 0; mf < MF; mf++)
                *(uint4*)af[mf] = *(const uint4*)&Asm[(kc*MBLKS + wm*MF + mf)*128 + lane*4];
            #pragma unroll
            for (int np = 0; np < NF/2; np++) {
                uint4 bv = *(const uint4*)&Bsm[(kc*NPB + wn*(NF/2) + np)*128 + lane*4];
                uint32_t* bf = (uint32_t*)&bv;
                #pragma unroll
                for (int mf = 0; mf < MF; mf++) {
                    mma_tf32(acc[mf][2*np],   af[mf], bf);
                    mma_tf32(acc[mf][2*np+1], af[mf], bf + 2);
                }
            }
        }
        __syncthreads();
    }

    /* ---- epilogue ---- */
    float* rowbuf = (float*)dsm;   /* LNOUT: reuse staging smem, stride 66 */
    int r = lane >> 2, c2 = (lane & 3)*2;
    #pragma unroll
    for (int mf = 0; mf < MF; mf++) {
        int mrow = m0 + wm*(MF*16) + mf*16 + r;
        #pragma unroll
        for (int nf = 0; nf < NF; nf++) {
            int nout = n0 + wn*WN + nf*8 + c2;
            float v00 = acc[mf][nf][0], v01 = acc[mf][nf][1];
            float v10 = acc[mf][nf][2], v11 = acc[mf][nf][3];
            if (BIAS_) {
                float2 bb = *(const float2*)&bias[nout];
                v00 += bb.x; v01 += bb.y; v10 += bb.x; v11 += bb.y;
            }
            if (GELU_) {
                v00 = 0.5f*v00*(1.0f + erff(v00*0.70710678118654752f));
                v01 = 0.5f*v01*(1.0f + erff(v01*0.70710678118654752f));
                v10 = 0.5f*v10*(1.0f + erff(v10*0.70710678118654752f));
                v11 = 0.5f*v11*(1.0f + erff(v11*0.70710678118654752f));
            }
            if (QV_ && nout < 512) {
                int d = nout & 63;
                int b0 = (mrow/NTOK) & 63;
                int b1 = ((mrow+8)/NTOK) & 63;
                float2 s0 = *(const float2*)&g_sdfm[b0*64 + d];
                float2 s1 = *(const float2*)&g_sdfm[b1*64 + d];
                v00 *= s0.x; v01 *= s0.y; v10 *= s1.x; v11 *= s1.y;
            }
            int nc = QV_ ? (nout & 511) : nout;
            if (OUT == 1) {
                uint16_t* dst = (uint16_t*)(QV_ ? (nout < 512 ? Cp_ : C2p_) : Cp_);
                uint32_t pk0, pk1;
                PACKBF(pk0, v00, v01);
                PACKBF(pk1, v10, v11);
                *(uint32_t*)(dst + (size_t)mrow*ldc + nc)     = pk0;
                *(uint32_t*)(dst + (size_t)(mrow+8)*ldc + nc) = pk1;
            } else {
                float* dst = (float*)Cp_;
                float* p0 = dst + (size_t)mrow*ldc + nc;
                float* p1 = dst + (size_t)(mrow+8)*ldc + nc;
                if (ACC_) {
                    float2 o0 = *(float2*)p0, o1 = *(float2*)p1;
                    v00 += o0.x; v01 += o0.y; v10 += o1.x; v11 += o1.y;
                }
                float2 s0; s0.x = v00; s0.y = v01;
                float2 s1; s1.x = v10; s1.y = v11;
                *(float2*)p0 = s0;
                *(float2*)p1 = s1;
                if (LNOUT) {
                    int mr0 = mrow - m0, mr1 = mr0 + 8;
                    rowbuf[mr0*66 + nout]     = v00;
                    rowbuf[mr0*66 + nout + 1] = v01;
                    rowbuf[mr1*66 + nout]     = v10;
                    rowbuf[mr1*66 + nout + 1] = v11;
                }
            }
        }
    }

    if (LNOUT) {
        __syncthreads();
        float lg0 = lngamma[lane], lg1 = lngamma[lane+32];
        float lb0 = lnbeta[lane],  lb1 = lnbeta[lane+32];
        #pragma unroll 1
        for (int i = 0; i < BM/8; i++) {
            int rr = w*(BM/8) + i;
            float x0 = rowbuf[rr*66 + lane], x1 = rowbuf[rr*66 + lane + 32];
            float s = x0 + x1;
            #pragma unroll
            for (int o = 16; o; o >>= 1) s += __shfl_xor_sync(0xffffffffu, s, o);
            float mean = s * (1.0f/64.0f);
            float d0 = x0 - mean, d1 = x1 - mean;
            float vv = d0*d0 + d1*d1;
            #pragma unroll
            for (int o = 16; o; o >>= 1) vv += __shfl_xor_sync(0xffffffffu, vv, o);
            float ri = rsqrtf(vv*(1.0f/64.0f) + EPSV);
            int m = m0 + rr;
            g_XNf[gword(m, lane)]    = totf(d0*ri*lg0 + lb0);
            g_XNf[gword(m, lane+32)] = totf(d1*ri*lg1 + lb1);
        }
    }
}

/* ---------------- bf16 mma.sync fused attention (Q pre-scaled) ---------------- */
#define QSTRIDE 72
#define QBYTES  (256*QSTRIDE*2)
#define ATT_BYTES (2*QBYTES)

__global__ void __launch_bounds__(512) attn_kernel() {
    extern __shared__ char smc[];
    uint16_t* Qh = (uint16_t*)smc;
    uint16_t* Vh = (uint16_t*)(smc + QBYTES);
    uint32_t vbase = smem_u32(smc) + QBYTES;

    int t = threadIdx.x;
    int bh = blockIdx.x;
    int bp = bh >> 3, h = bh & 7;
    uint16_t* Qb = g_Q + (size_t)bp*NTOK*INNER + h*DHEAD;
    const uint16_t* Vb = g_V + (size_t)bp*NTOK*INNER + h*DHEAD;

    /* stage: straight uint4 copies (Q already scaled by QV epilogue) */
    for (int f = t; f < NTOK*8; f += 512) {
        int n = f >> 3, d8 = (f & 7)*8;
        *(uint4*)&Qh[n*QSTRIDE + d8] = *(const uint4*)(Qb + (size_t)n*INNER + d8);
    }
    for (int f = t; f < NTOK*8; f += 512) {
        int n = f >> 3, d8 = (f & 7)*8;
        *(uint4*)&Vh[n*QSTRIDE + d8] = *(const uint4*)(Vb + (size_t)n*INNER + d8);
    }
    {
        uint32_t* qz = (uint32_t*)(Qh + NTOK*QSTRIDE);
        uint32_t* vz = (uint32_t*)(Vh + NTOK*QSTRIDE);
        for (int f = t; f < (256 - NTOK)*QSTRIDE/2; f += 512) { qz[f] = 0u; vz[f] = 0u; }
    }
    __syncthreads();

    int lane = t & 31;
    int wid  = t >> 5;
    int m0   = wid*16;
    int r    = lane >> 2;
    int c2   = (lane & 3)*2;

    uint32_t qa[4][4];
    #pragma unroll
    for (int kb = 0; kb < 4; kb++) {
        const uint16_t* qrow = Qh + (m0 + r)*QSTRIDE + kb*16 + c2;
        qa[kb][0] = *(const uint32_t*)(qrow);
        qa[kb][1] = *(const uint32_t*)(qrow + 8*QSTRIDE);
        qa[kb][2] = *(const uint32_t*)(qrow + 8);
        qa[kb][3] = *(const uint32_t*)(qrow + 8*QSTRIDE + 8);
    }

    float O[8][4];
    #pragma unroll
    for (int nt = 0; nt < 8; nt++)
        #pragma unroll
        for (int j = 0; j < 4; j++) O[nt][j] = 0.f;
    float rs0 = 0.f, rs1 = 0.f;

    for (int ch = 0; ch < 4; ch++) {
        float S[8][4];
        #pragma unroll
        for (int nt = 0; nt < 8; nt++)
            #pragma unroll
            for (int j = 0; j < 4; j++) S[nt][j] = 0.f;
        #pragma unroll
        for (int kb = 0; kb < 4; kb++) {
            #pragma unroll
            for (int nt = 0; nt < 8; nt++) {
                const uint16_t* brow = Qh + (ch*64 + nt*8 + r)*QSTRIDE + kb*16 + c2;
                uint32_t b[2] = { *(const uint32_t*)brow, *(const uint32_t*)(brow + 8) };
                mma_bf16(S[nt], qa[kb], b);
            }
        }
        uint32_t pa[4][4];
        #pragma unroll
        for (int nt = 0; nt < 8; nt++) {
            int col = ch*64 + nt*8 + c2;
            float e0 = (col     < NTOK) ? __expf(S[nt][0]) : 0.f;
            float e1 = (col + 1 < NTOK) ? __expf(S[nt][1]) : 0.f;
            float e2 = (col     < NTOK) ? __expf(S[nt][2]) : 0.f;
            float e3 = (col + 1 < NTOK) ? __expf(S[nt][3]) : 0.f;
            rs0 += e0 + e1;
            rs1 += e2 + e3;
            uint32_t plo, phi;
            PACKBF(plo, e0, e1);
            PACKBF(phi, e2, e3);
            pa[nt >> 1][(nt & 1)*2]     = plo;
            pa[nt >> 1][(nt & 1)*2 + 1] = phi;
        }
        #pragma unroll
        for (int kb = 0; kb < 4; kb++) {
            uint32_t vb[16];
            int krow = ch*64 + kb*16 + (lane & 15);
            int coff = 8*(lane >> 4);
            #pragma unroll
            for (int q = 0; q < 4; q++)
                ldm_x4_trans(vb + q*4, vbase + (uint32_t)(krow*QSTRIDE + q*16 + coff)*2);
            #pragma unroll
            for (int nt = 0; nt < 8; nt++)
                mma_bf16(O[nt], pa[kb], &vb[(nt >> 1)*4 + (nt & 1)*2]);
        }
    }

    #pragma unroll
    for (int o = 1; o <= 2; o <<= 1) {
        rs0 += __shfl_xor_sync(0xffffffffu, rs0, o);
        rs1 += __shfl_xor_sync(0xffffffffu, rs1, o);
    }
    float ri0 = 1.0f/rs0, ri1 = 1.0f/rs1;
    int i0 = m0 + r;
    if (i0 < NTOK) {
        uint16_t* op = Qb + (size_t)i0*INNER;
        #pragma unroll
        for (int nt = 0; nt < 8; nt++) {
            uint32_t pk;
            PACKBF(pk, O[nt][0]*ri0, O[nt][1]*ri0);
            *(uint32_t*)(op + nt*8 + c2) = pk;
        }
    }
    if (i0 + 8 < NTOK) {
        uint16_t* op = Qb + (size_t)(i0 + 8)*INNER;
        #pragma unroll
        for (int nt = 0; nt < 8; nt++) {
            uint32_t pk;
            PACKBF(pk, O[nt][2]*ri1, O[nt][3]*ri1);
            *(uint32_t*)(op + nt*8 + c2) = pk;
        }
    }
}

/* ---------------- token exchange (X + XNf) + final ---------------- */
__global__ void swap_cls_kernel() {
    int idx = blockIdx.x*blockDim.x + threadIdx.x;
    if (idx >= BATCH*64) return;
    int b = idx >> 6, c = idx & 63;
    int m0_ = b*NTOK, m1_ = (b+BATCH)*NTOK;
    size_t i0 = (size_t)m0_*64 + c;
    size_t i1 = (size_t)m1_*64 + c;
    float a = g_X[i0], d = g_X[i1];
    g_X[i0] = d; g_X[i1] = a;
    uint32_t w0 = gword(m0_, c), w1 = gword(m1_, c);
    uint32_t u = g_XNf[w0], v = g_XNf[w1];
    g_XNf[w0] = v; g_XNf[w1] = u;
}

__global__ void final_kernel(float* __restrict__ out) {
    int idx = blockIdx.x*blockDim.x + threadIdx.x;
    if (idx >= BATCH*64) return;
    int b = idx >> 6, c = idx & 63;
    out[idx] = g_X[(size_t)b*NTOK*64 + c] + g_X[(size_t)(b+BATCH)*NTOK*64 + c];
}

/* ---------------- host ---------------- */
extern "C" void kernel_launch(void* const* d_in, const int* in_sizes, int n_in,
                              void* d_out, int out_size)
{
    const float* hsi       = (const float*)d_in[0];
    const float* lidar     = (const float*)d_in[1];
    const float* cls_hsi   = (const float*)d_in[2];
    const float* cls_lidar = (const float*)d_in[3];
    const float* pos_hsi   = (const float*)d_in[4];
    const float* pos_lidar = (const float*)d_in[5];
    const float* fmg_w     = (const float*)d_in[6];
    const float* ln1_g     = (const float*)d_in[7];
    const float* ln1_b     = (const float*)d_in[8];
    const float* qkv_w     = (const float*)d_in[9];
    const float* out_w     = (const float*)d_in[10];
    const float* out_b     = (const float*)d_in[11];
    const float* ln2_g     = (const float*)d_in[12];
    const float* ln2_b     = (const float*)d_in[13];
    const float* ff_w1     = (const float*)d_in[14];
    const float* ff_b1     = (const float*)d_in[15];
    const float* ff_w2     = (const float*)d_in[16];
    const float* ff_b2     = (const float*)d_in[17];

    float *X;
    uint32_t *XNf, *Wf;
    uint16_t *Qb, *Vb, *Hb;
    cudaGetSymbolAddress((void**)&X,   g_X);
    cudaGetSymbolAddress((void**)&XNf, g_XNf);
    cudaGetSymbolAddress((void**)&Qb,  g_Q);
    cudaGetSymbolAddress((void**)&Vb,  g_V);
    cudaGetSymbolAddress((void**)&Hb,  g_H);
    cudaGetSymbolAddress((void**)&Wf,  g_Wfrag);

    cudaFuncSetAttribute(attn_kernel, cudaFuncAttributeMaxDynamicSharedMemorySize, ATT_BYTES);
    cudaFuncSetAttribute(tgemm<128,128,false,false,false,true,2,1,false>,
                         cudaFuncAttributeMaxDynamicSharedMemorySize, 65536);
    cudaFuncSetAttribute(tgemm<128,128,true,false,true,false,2,1,false>,
                         cudaFuncAttributeMaxDynamicSharedMemorySize, 65536);
    cudaFuncSetAttribute(tgemm<64,64,false,true,true,false,1,0,true>,
                         cudaFuncAttributeMaxDynamicSharedMemorySize, 32768);

    mean_kernel<<<32, 256>>>(hsi, lidar);
    dfm_kernel<<<16, 256>>>(fmg_w);
    build_kernel<<<(M2*DIMC + 255)/256, 256>>>(hsi, cls_hsi, cls_lidar, pos_hsi, pos_lidar);
    ln_frag_kernel<<<M2/8, 256>>>(X, ln1_g, ln1_b);

    prep_qv<<<DEPTH*64*1024/256, 256>>>(qkv_w);
    prep_gen<<<DEPTH*512*64/256, 256>>>(out_w, 512, 64, OFF_PROJ, DEPTH*512*64);
    prep_gen<<<DEPTH*64*256/256, 256>>>(ff_w1, 64, 256, OFF_FF1, DEPTH*64*256);
    prep_gen<<<DEPTH*256*64/256, 256>>>(ff_w2, 256, 64, OFF_FF2, DEPTH*256*64);

    for (int phase = 0; phase < 2; phase++) {
        for (int L = 0; L < DEPTH; L++) {
            const uint32_t* WL = Wf + (size_t)L*131072;
            int Ln = (L + 1) & 3;
            /* QV (A = XNf frag, Q scaled by sd in epilogue) */
            tgemm<128,128,false,false,false,true,2,1,false><<<dim3(8,226), 256, 65536>>>(
                XNf, WL + OFF_QV, nullptr, Qb, Vb, nullptr, nullptr, 64, 0, 1024, 512);
            attn_kernel<<<1024, 512, ATT_BYTES>>>();
            /* proj + residual + fused LN2 -> XNf */
            tgemm<64,64,false,true,true,false,1,0,true><<<dim3(1,452), 256, 32768>>>(
                Qb, WL + OFF_PROJ, out_b + L*64, X, nullptr,
                ln2_g + L*64, ln2_b + L*64, 512, 512, 64, 64);
            /* ff1 (A = XNf frag) + GELU */
            tgemm<128,128,true,false,true,false,2,1,false><<<dim3(2,226), 256, 65536>>>(
                XNf, WL + OFF_FF1, ff_b1 + L*256, Hb, nullptr, nullptr, nullptr, 64, 0, 256, 256);
            /* ff2 + residual + fused LN1(next layer) -> XNf */
            tgemm<64,64,false,true,true,false,1,0,true><<<dim3(1,452), 256, 32768>>>(
                Hb, WL + OFF_FF2, ff_b2 + L*64, X, nullptr,
                ln1_g + Ln*64, ln1_b + Ln*64, 256, 256, 64, 64);
        }
        if (phase == 0) swap_cls_kernel<<<16, 256>>>();
    }
    final_kernel<<<16, 256>>>((float*)d_out);
}

// round 13
// speedup vs baseline: 1.2421x; 1.2421x over previous
#include <cuda_runtime.h>
#include <cuda_bf16.h>
#include <math.h>
#include <cstdint>

#define BATCH   64
#define DIMC    64
#define HEADS   8
#define DHEAD   64
#define INNER   512
#define MLPD    256
#define DEPTH   4
#define NPATCH  225
#define NTOK    226
#define M2      (2*BATCH*NTOK)   /* 28928 rows */
#define MBTOT   (M2/16)          /* 1808 m-blocks */
#define EPSV    1e-5f
#define SCALEV  0.125f

/* ---------------- mma helpers ---------------- */
__device__ __forceinline__ uint32_t smem_u32(const void* p) {
    uint32_t a;
    asm("{ .reg .u64 t; cvta.to.shared.u64 t, %1; cvt.u32.u64 %0, t; }" : "=r"(a) : "l"(p));
    return a;
}
__device__ __forceinline__ void mma_bf16(float* c, const uint32_t* a, const uint32_t* b) {
    asm volatile("mma.sync.aligned.m16n8k16.row.col.f32.bf16.bf16.f32 "
        "{%0,%1,%2,%3}, {%4,%5,%6,%7}, {%8,%9}, {%0,%1,%2,%3};"
        : "+f"(c[0]), "+f"(c[1]), "+f"(c[2]), "+f"(c[3])
        : "r"(a[0]), "r"(a[1]), "r"(a[2]), "r"(a[3]), "r"(b[0]), "r"(b[1]));
}
__device__ __forceinline__ void mma_tf32(float* c, const uint32_t* a, const uint32_t* b) {
    asm volatile("mma.sync.aligned.m16n8k8.row.col.f32.tf32.tf32.f32 "
        "{%0,%1,%2,%3}, {%4,%5,%6,%7}, {%8,%9}, {%0,%1,%2,%3};"
        : "+f"(c[0]), "+f"(c[1]), "+f"(c[2]), "+f"(c[3])
        : "r"(a[0]), "r"(a[1]), "r"(a[2]), "r"(a[3]), "r"(b[0]), "r"(b[1]));
}
__device__ __forceinline__ void ldm_x4_trans(uint32_t* r, uint32_t addr) {
    asm volatile("ldmatrix.sync.aligned.m8n8.x4.trans.shared.b16 {%0,%1,%2,%3}, [%4];"
        : "=r"(r[0]), "=r"(r[1]), "=r"(r[2]), "=r"(r[3]) : "r"(addr));
}
__device__ __forceinline__ uint32_t totf(float x) {
    uint32_t r; asm("cvt.rna.tf32.f32 %0, %1;" : "=r"(r) : "f"(x)); return r;
}
#define PACKBF(r, lo_, hi_) asm("cvt.rn.bf16x2.f32 %0, %1, %2;" : "=r"(r) : "f"(hi_), "f"(lo_))

/* tf32 fragment-layout word index (verified R5/R7) */
__host__ __device__ inline int faddr(int k, int n, int npairs) {
    return ((k>>3)*npairs + (n>>4))*128 + ((n&7)*4 + (k&3))*4 + (((n>>3)&1)*2) + ((k>>2)&1);
}
/* A-fragment word index in global XNf (m rows over MBTOT blocks) */
__device__ __forceinline__ uint32_t gword(int m, int k) {
    return (uint32_t)(((k>>3)*MBTOT + (m>>4))*128 + (m&7)*16 + ((m>>3)&1) + ((k>>2)&1)*2 + (k&3)*4);
}

/* ---------------- scratch ---------------- */
__device__ float    g_X  [(size_t)M2*DIMC];
__device__ uint32_t g_XNf[(size_t)M2*DIMC];   /* LN output, tf32 frag-order (ff1 A)   */
__device__ uint16_t g_XNh[(size_t)M2*DIMC];   /* LN output, bf16 row-major (attn A)   */
__device__ uint16_t g_Q [(size_t)M2*INNER];   /* attn O output (bf16), proj A         */
__device__ uint16_t g_H [(size_t)M2*MLPD];    /* bf16 */
__device__ float    g_sdfm[BATCH*DIMC];
__device__ float    g_xmean[BATCH*2*DIMC];
/* per layer 98304 words: QV bf16-frag @0 (32768), proj tf32 @32768 (32768),
   ff1 @65536 (16384), ff2 @81920 (16384) */
#define PERL     98304
#define OFF_QV   0
#define OFF_PROJ 32768
#define OFF_FF1  65536
#define OFF_FF2  81920
__device__ uint32_t g_Wfrag[(size_t)DEPTH*PERL];

/* ---------------- prologue ---------------- */
__global__ void mean_kernel(const float* __restrict__ hsi, const float* __restrict__ lidar) {
    int idx = blockIdx.x*blockDim.x + threadIdx.x;
    if (idx >= BATCH*128) return;
    int b = idx >> 7, c = idx & 127;
    const float* src = (c < 64) ? (hsi + ((size_t)b*64 + c)*NPATCH)
                                : (lidar + ((size_t)b*64 + (c-64))*NPATCH);
    float s = 0.f;
    for (int p = 0; p < NPATCH; p++) s += src[p];
    g_xmean[idx] = s * (1.0f/NPATCH);
}

__global__ void dfm_kernel(const float* __restrict__ fmg_w) {
    int idx = blockIdx.x*blockDim.x + threadIdx.x;
    if (idx >= BATCH*64) return;
    int b = idx >> 6, d = idx & 63;
    const float* xm = g_xmean + b*128;
    const float* wc = fmg_w + d*65;
    float s = 0.f;
    for (int c = 0; c < 128; c++) s += xm[c] * wc[(size_t)c*4096];
    float sig = 1.0f/(1.0f + expf(-s));
    g_sdfm[idx] = sqrtf(sig * SCALEV);
}

__global__ void build_kernel(const float* __restrict__ hsi,
                             const float* __restrict__ cls_hsi, const float* __restrict__ cls_lidar,
                             const float* __restrict__ pos_hsi, const float* __restrict__ pos_lidar) {
    int idx = blockIdx.x*blockDim.x + threadIdx.x;
    if (idx >= M2*DIMC) return;
    int c  = idx & 63;
    int n  = (idx >> 6) % NTOK;
    int bp = idx / (NTOK*64);
    int b  = bp & 63;
    int br = bp >> 6;
    const float* cls = br ? cls_lidar : cls_hsi;
    const float* pos = br ? pos_lidar : pos_hsi;
    float v = (n == 0) ? cls[c] : hsi[((size_t)b*64 + c)*NPATCH + (n-1)];
    g_X[idx] = v + pos[n*64 + c];
}

/* ---------------- layernorm -> XNf (tf32 frag) + XNh (bf16 rows) ---------------- */
__global__ void ln_frag_kernel(const float* __restrict__ Xp,
                               const float* __restrict__ g, const float* __restrict__ bb) {
    int w = threadIdx.x >> 5, lane = threadIdx.x & 31;
    int row = blockIdx.x*8 + w;
    const float* xr = Xp + (size_t)row*64;
    float x0 = xr[lane], x1 = xr[lane+32];
    float s = x0 + x1;
    #pragma unroll
    for (int o = 16; o; o >>= 1) s += __shfl_xor_sync(0xffffffffu, s, o);
    float m = s * (1.0f/64.0f);
    float d0 = x0 - m, d1 = x1 - m;
    float v = d0*d0 + d1*d1;
    #pragma unroll
    for (int o = 16; o; o >>= 1) v += __shfl_xor_sync(0xffffffffu, v, o);
    float r = rsqrtf(v*(1.0f/64.0f) + EPSV);
    float y0 = d0*r*g[lane]    + bb[lane];
    float y1 = d1*r*g[lane+32] + bb[lane+32];
    g_XNf[gword(row, lane)]    = totf(y0);
    g_XNf[gword(row, lane+32)] = totf(y1);
    __nv_bfloat16 h0 = __float2bfloat16(y0), h1 = __float2bfloat16(y1);
    g_XNh[(size_t)row*64 + lane]      = *(uint16_t*)&h0;
    g_XNh[(size_t)row*64 + lane + 32] = *(uint16_t*)&h1;
}

/* ---------------- weight prep ---------------- */
/* QV weights -> bf16 B-fragment layout (m16n8k16): word index
   ((kb*128 + j)*32 + lane)*2 + h, value = pack(w[k][n], w[k+1][n]),
   k = kb*16 + (lane&3)*2 + h*8, n = j*8 + (lane>>2); j<64 -> Q col, j>=64 -> V col. */
__global__ void prep_qv(const float* __restrict__ qkv_w) {
    int idx = blockIdx.x*blockDim.x + threadIdx.x;
    if (idx >= DEPTH*32768) return;
    int h_ = idx & 1;
    int l  = (idx >> 1) & 31;
    int j  = (idx >> 6) & 127;
    int kb = (idx >> 13) & 3;
    int L  = idx >> 15;
    int k = kb*16 + (l & 3)*2 + h_*8;
    int n = j*8 + (l >> 2);
    int col = (n < 512) ? n : n + 512;
    const float* wp = qkv_w + (size_t)L*64*1536;
    float w0 = wp[(size_t)k*1536 + col];
    float w1 = wp[(size_t)(k+1)*1536 + col];
    uint32_t pk; PACKBF(pk, w0, w1);
    g_Wfrag[(size_t)L*PERL + OFF_QV + idx % 32768] = pk;
}
__global__ void prep_gen(const float* __restrict__ w, int K, int N, int dstoff, int total) {
    int idx = blockIdx.x*blockDim.x + threadIdx.x;
    if (idx >= total) return;
    int kn = K*N;
    int L = idx / kn, rem = idx % kn;
    int k = rem / N, n = rem % N;
    g_Wfrag[(size_t)L*PERL + dstoff + faddr(k, n, N >> 4)] = totf(w[(size_t)idx]);
}

/* ---------------- tf32 mma GEMM (proj/ff1/ff2) ----------------
   AIN: 1 = bf16 A, 2 = frag-order tf32 A (bulk copy).
   OUT: 0 = fp32 C (ACC), 1 = bf16 C.
   LNOUT: fused residual+LN -> g_XNf; XNH_: also write g_XNh. */
template<int BM, int BN, bool GELU_, bool ACC_, bool BIAS_, int AIN, int OUT, bool LNOUT, bool XNH_>
__global__ void __launch_bounds__(256) tgemm(
    const void* __restrict__ Ap, const uint32_t* __restrict__ Bf,
    const float* __restrict__ bias, void* __restrict__ Cp_,
    const float* __restrict__ lngamma, const float* __restrict__ lnbeta,
    int K, int lda, int Ntot, int ldc)
{
    constexpr int MBLKS = BM/16;
    constexpr int NPB   = BN/16;
    constexpr int MF    = BM/64;
    constexpr int WN    = BN/2;
    constexpr int NF    = WN/8;
    const int NPAIRS = Ntot >> 4;

    extern __shared__ uint32_t dsm[];
    uint32_t* Asm = dsm;
    uint32_t* Bsm = dsm + 8*MBLKS*128;

    int t = threadIdx.x, lane = t & 31, w = t >> 5;
    int wm = w & 3, wn = w >> 2;
    int m0 = blockIdx.y * BM;
    int n0 = blockIdx.x * BN;
    int np0 = n0 >> 4;

    float acc[MF][NF][4];
    #pragma unroll
    for (int i = 0; i < MF; i++)
        #pragma unroll
        for (int j = 0; j < NF; j++)
            #pragma unroll
            for (int q = 0; q < 4; q++) acc[i][j][q] = 0.f;

    for (int kt = 0; kt < K; kt += 64) {
        if (AIN == 1) {
            #pragma unroll
            for (int it = 0; it < BM/32; it++) {
                int idx = t + it*256;
                int m = idx >> 3, k8 = (idx & 7)*8;
                uint4 v = *(const uint4*)((const uint16_t*)Ap + (size_t)(m0+m)*lda + kt + k8);
                const uint16_t* hp = (const uint16_t*)&v;
                int base = ((k8>>3)*MBLKS + (m>>4))*128 + (m&7)*16 + ((m>>3)&1);
                #pragma unroll
                for (int j = 0; j < 8; j++)
                    Asm[base + (j>>2)*2 + (j&3)*4] = ((uint32_t)hp[j]) << 16;
            }
        } else {
            const uint4* Afr = (const uint4*)Ap;
            int mb0 = m0 >> 4;
            #pragma unroll
            for (int it = 0; it < MBLKS; it++) {
                int i = t + it*256;
                int kc = i / (MBLKS*32);
                int rem = i % (MBLKS*32);
                ((uint4*)Asm)[i] = __ldg(Afr + (size_t)(kc*MBTOT + mb0 + (rem>>5))*32 + (rem&31));
            }
        }
        int kc0 = kt >> 3;
        #pragma unroll
        for (int it = 0; it < NPB; it++) {
            int i = t + it*256;
            int kc = i / (NPB*32);
            int rem = i % (NPB*32);
            int np = rem >> 5, l4 = rem & 31;
            ((uint4*)Bsm)[i] = __ldg((const uint4*)(Bf + (size_t)((kc0+kc)*NPAIRS + np0 + np)*128 + l4*4));
        }
        __syncthreads();

        #pragma unroll
        for (int kc = 0; kc < 8; kc++) {
            uint32_t af[MF][4];
            #pragma unroll
            for (int mf = 0; mf < MF; mf++)
                *(uint4*)af[mf] = *(const uint4*)&Asm[(kc*MBLKS + wm*MF + mf)*128 + lane*4];
            #pragma unroll
            for (int np = 0; np < NF/2; np++) {
                uint4 bv = *(const uint4*)&Bsm[(kc*NPB + wn*(NF/2) + np)*128 + lane*4];
                uint32_t* bf = (uint32_t*)&bv;
                #pragma unroll
                for (int mf = 0; mf < MF; mf++) {
                    mma_tf32(acc[mf][2*np],   af[mf], bf);
                    mma_tf32(acc[mf][2*np+1], af[mf], bf + 2);
                }
            }
        }
        __syncthreads();
    }

    float* rowbuf = (float*)dsm;
    int r = lane >> 2, c2 = (lane & 3)*2;
    #pragma unroll
    for (int mf = 0; mf < MF; mf++) {
        int mrow = m0 + wm*(MF*16) + mf*16 + r;
        #pragma unroll
        for (int nf = 0; nf < NF; nf++) {
            int nout = n0 + wn*WN + nf*8 + c2;
            float v00 = acc[mf][nf][0], v01 = acc[mf][nf][1];
            float v10 = acc[mf][nf][2], v11 = acc[mf][nf][3];
            if (BIAS_) {
                float2 bb = *(const float2*)&bias[nout];
                v00 += bb.x; v01 += bb.y; v10 += bb.x; v11 += bb.y;
            }
            if (GELU_) {
                v00 = 0.5f*v00*(1.0f + erff(v00*0.70710678118654752f));
                v01 = 0.5f*v01*(1.0f + erff(v01*0.70710678118654752f));
                v10 = 0.5f*v10*(1.0f + erff(v10*0.70710678118654752f));
                v11 = 0.5f*v11*(1.0f + erff(v11*0.70710678118654752f));
            }
            if (OUT == 1) {
                uint16_t* dst = (uint16_t*)Cp_;
                uint32_t pk0, pk1;
                PACKBF(pk0, v00, v01);
                PACKBF(pk1, v10, v11);
                *(uint32_t*)(dst + (size_t)mrow*ldc + nout)     = pk0;
                *(uint32_t*)(dst + (size_t)(mrow+8)*ldc + nout) = pk1;
            } else {
                float* dst = (float*)Cp_;
                float* p0 = dst + (size_t)mrow*ldc + nout;
                float* p1 = dst + (size_t)(mrow+8)*ldc + nout;
                if (ACC_) {
                    float2 o0 = *(float2*)p0, o1 = *(float2*)p1;
                    v00 += o0.x; v01 += o0.y; v10 += o1.x; v11 += o1.y;
                }
                float2 s0; s0.x = v00; s0.y = v01;
                float2 s1; s1.x = v10; s1.y = v11;
                *(float2*)p0 = s0;
                *(float2*)p1 = s1;
                if (LNOUT) {
                    int mr0 = mrow - m0, mr1 = mr0 + 8;
                    rowbuf[mr0*66 + nout]     = v00;
                    rowbuf[mr0*66 + nout + 1] = v01;
                    rowbuf[mr1*66 + nout]     = v10;
                    rowbuf[mr1*66 + nout + 1] = v11;
                }
            }
        }
    }

    if (LNOUT) {
        __syncthreads();
        float lg0 = lngamma[lane], lg1 = lngamma[lane+32];
        float lb0 = lnbeta[lane],  lb1 = lnbeta[lane+32];
        #pragma unroll 1
        for (int i = 0; i < BM/8; i++) {
            int rr = w*(BM/8) + i;
            float x0 = rowbuf[rr*66 + lane], x1 = rowbuf[rr*66 + lane + 32];
            float s = x0 + x1;
            #pragma unroll
            for (int o = 16; o; o >>= 1) s += __shfl_xor_sync(0xffffffffu, s, o);
            float mean = s * (1.0f/64.0f);
            float d0 = x0 - mean, d1 = x1 - mean;
            float vv = d0*d0 + d1*d1;
            #pragma unroll
            for (int o = 16; o; o >>= 1) vv += __shfl_xor_sync(0xffffffffu, vv, o);
            float ri = rsqrtf(vv*(1.0f/64.0f) + EPSV);
            int m = m0 + rr;
            float y0 = d0*ri*lg0 + lb0;
            float y1 = d1*ri*lg1 + lb1;
            g_XNf[gword(m, lane)]    = totf(y0);
            g_XNf[gword(m, lane+32)] = totf(y1);
            if (XNH_) {
                __nv_bfloat16 h0 = __float2bfloat16(y0), h1 = __float2bfloat16(y1);
                g_XNh[(size_t)m*64 + lane]      = *(uint16_t*)&h0;
                g_XNh[(size_t)m*64 + lane + 32] = *(uint16_t*)&h1;
            }
        }
    }
}

/* ---------------- fused QV + attention ----------------
   One CTA per (bp, h), 512 threads. Stages XN (bf16 rows, 36KB), computes
   Q = XN@Wq (scaled by sqrt(dfm*SCALE)) and V = XN@Wv via bf16 mma into smem,
   then S = QQ^T, softmax(exp, unnormalized), O = PV, writes O bf16 to g_Q. */
#define XSTRIDE 72
#define XBUF    36864                    /* 256*72*2 */
#define ATT_BYTES (3*XBUF)               /* Xh + Qh + Vh = 110592 */

__global__ void __launch_bounds__(512) attn_kernel(const uint32_t* __restrict__ Wqv) {
    extern __shared__ char smc[];
    uint16_t* Xh = (uint16_t*)smc;
    uint16_t* Qh = (uint16_t*)(smc + XBUF);
    uint16_t* Vh = (uint16_t*)(smc + 2*XBUF);
    uint32_t vbase = smem_u32(smc) + 2*XBUF;

    int t = threadIdx.x;
    int bh = blockIdx.x;
    int bp = bh >> 3, h = bh & 7;
    int bidx = bp & 63;
    uint16_t* Ob = g_Q + (size_t)bp*NTOK*INNER + h*DHEAD;
    const uint16_t* Xg = g_XNh + (size_t)bp*NTOK*64;

    /* stage XN rows (bf16), zero tail rows */
    for (int f = t; f < NTOK*8; f += 512) {
        int n = f >> 3, d8 = (f & 7)*8;
        *(uint4*)&Xh[n*XSTRIDE + d8] = *(const uint4*)(Xg + (size_t)n*64 + d8);
    }
    if (t < 270) ((uint4*)(Xh + NTOK*XSTRIDE))[t] = make_uint4(0,0,0,0);
    __syncthreads();

    int lane = t & 31, wid = t >> 5;
    int m0 = wid*16, r = lane >> 2, c2 = (lane & 3)*2;

    /* ---- QV: per warp 16 rows ---- */
    {
        uint32_t xa[4][4];
        #pragma unroll
        for (int kb = 0; kb < 4; kb++) {
            const uint16_t* xrow = Xh + (m0 + r)*XSTRIDE + kb*16 + c2;
            xa[kb][0] = *(const uint32_t*)(xrow);
            xa[kb][1] = *(const uint32_t*)(xrow + 8*XSTRIDE);
            xa[kb][2] = *(const uint32_t*)(xrow + 8);
            xa[kb][3] = *(const uint32_t*)(xrow + 8*XSTRIDE + 8);
        }
        /* Q: j-blocks h*8 .. h*8+7, scaled by sdfm */
        float qc[8][4];
        #pragma unroll
        for (int j = 0; j < 8; j++)
            #pragma unroll
            for (int q = 0; q < 4; q++) qc[j][q] = 0.f;
        #pragma unroll
        for (int kb = 0; kb < 4; kb++)
            #pragma unroll
            for (int j = 0; j < 8; j++) {
                uint2 bw = __ldg((const uint2*)(Wqv + (size_t)(((kb*128) + h*8 + j)*32 + lane)*2));
                mma_bf16(qc[j], xa[kb], (const uint32_t*)&bw);
            }
        #pragma unroll
        for (int j = 0; j < 8; j++) {
            int d = j*8 + c2;
            float2 sd = *(const float2*)&g_sdfm[bidx*64 + d];
            uint32_t p0, p1;
            PACKBF(p0, qc[j][0]*sd.x, qc[j][1]*sd.y);
            PACKBF(p1, qc[j][2]*sd.x, qc[j][3]*sd.y);
            *(uint32_t*)&Qh[(m0 + r)*XSTRIDE + d]     = p0;
            *(uint32_t*)&Qh[(m0 + r + 8)*XSTRIDE + d] = p1;
        }
        /* V: j-blocks 64 + h*8 .. */
        float vc[8][4];
        #pragma unroll
        for (int j = 0; j < 8; j++)
            #pragma unroll
            for (int q = 0; q < 4; q++) vc[j][q] = 0.f;
        #pragma unroll
        for (int kb = 0; kb < 4; kb++)
            #pragma unroll
            for (int j = 0; j < 8; j++) {
                uint2 bw = __ldg((const uint2*)(Wqv + (size_t)(((kb*128) + 64 + h*8 + j)*32 + lane)*2));
                mma_bf16(vc[j], xa[kb], (const uint32_t*)&bw);
            }
        #pragma unroll
        for (int j = 0; j < 8; j++) {
            int d = j*8 + c2;
            uint32_t p0, p1;
            PACKBF(p0, vc[j][0], vc[j][1]);
            PACKBF(p1, vc[j][2], vc[j][3]);
            *(uint32_t*)&Vh[(m0 + r)*XSTRIDE + d]     = p0;
            *(uint32_t*)&Vh[(m0 + r + 8)*XSTRIDE + d] = p1;
        }
    }
    __syncthreads();

    /* ---- attention ---- */
    uint32_t qa[4][4];
    #pragma unroll
    for (int kb = 0; kb < 4; kb++) {
        const uint16_t* qrow = Qh + (m0 + r)*XSTRIDE + kb*16 + c2;
        qa[kb][0] = *(const uint32_t*)(qrow);
        qa[kb][1] = *(const uint32_t*)(qrow + 8*XSTRIDE);
        qa[kb][2] = *(const uint32_t*)(qrow + 8);
        qa[kb][3] = *(const uint32_t*)(qrow + 8*XSTRIDE + 8);
    }

    float O[8][4];
    #pragma unroll
    for (int nt = 0; nt < 8; nt++)
        #pragma unroll
        for (int j = 0; j < 4; j++) O[nt][j] = 0.f;
    float rs0 = 0.f, rs1 = 0.f;

    for (int ch = 0; ch < 4; ch++) {
        float S[8][4];
        #pragma unroll
        for (int nt = 0; nt < 8; nt++)
            #pragma unroll
            for (int j = 0; j < 4; j++) S[nt][j] = 0.f;
        #pragma unroll
        for (int kb = 0; kb < 4; kb++) {
            #pragma unroll
            for (int nt = 0; nt < 8; nt++) {
                const uint16_t* brow = Qh + (ch*64 + nt*8 + r)*XSTRIDE + kb*16 + c2;
                uint32_t b[2] = { *(const uint32_t*)brow, *(const uint32_t*)(brow + 8) };
                mma_bf16(S[nt], qa[kb], b);
            }
        }
        uint32_t pa[4][4];
        #pragma unroll
        for (int nt = 0; nt < 8; nt++) {
            int col = ch*64 + nt*8 + c2;
            float e0 = (col     < NTOK) ? __expf(S[nt][0]) : 0.f;
            float e1 = (col + 1 < NTOK) ? __expf(S[nt][1]) : 0.f;
            float e2 = (col     < NTOK) ? __expf(S[nt][2]) : 0.f;
            float e3 = (col + 1 < NTOK) ? __expf(S[nt][3]) : 0.f;
            rs0 += e0 + e1;
            rs1 += e2 + e3;
            uint32_t plo, phi;
            PACKBF(plo, e0, e1);
            PACKBF(phi, e2, e3);
            pa[nt >> 1][(nt & 1)*2]     = plo;
            pa[nt >> 1][(nt & 1)*2 + 1] = phi;
        }
        #pragma unroll
        for (int kb = 0; kb < 4; kb++) {
            uint32_t vb[16];
            int krow = ch*64 + kb*16 + (lane & 15);
            int coff = 8*(lane >> 4);
            #pragma unroll
            for (int q = 0; q < 4; q++)
                ldm_x4_trans(vb + q*4, vbase + (uint32_t)(krow*XSTRIDE + q*16 + coff)*2);
            #pragma unroll
            for (int nt = 0; nt < 8; nt++)
                mma_bf16(O[nt], pa[kb], &vb[(nt >> 1)*4 + (nt & 1)*2]);
        }
    }

    #pragma unroll
    for (int o = 1; o <= 2; o <<= 1) {
        rs0 += __shfl_xor_sync(0xffffffffu, rs0, o);
        rs1 += __shfl_xor_sync(0xffffffffu, rs1, o);
    }
    float ri0 = 1.0f/rs0, ri1 = 1.0f/rs1;
    int i0 = m0 + r;
    if (i0 < NTOK) {
        uint16_t* op = Ob + (size_t)i0*INNER;
        #pragma unroll
        for (int nt = 0; nt < 8; nt++) {
            uint32_t pk;
            PACKBF(pk, O[nt][0]*ri0, O[nt][1]*ri0);
            *(uint32_t*)(op + nt*8 + c2) = pk;
        }
    }
    if (i0 + 8 < NTOK) {
        uint16_t* op = Ob + (size_t)(i0 + 8)*INNER;
        #pragma unroll
        for (int nt = 0; nt < 8; nt++) {
            uint32_t pk;
            PACKBF(pk, O[nt][2]*ri1, O[nt][3]*ri1);
            *(uint32_t*)(op + nt*8 + c2) = pk;
        }
    }
}

/* ---------------- token exchange (X + XNf + XNh) + final ---------------- */
__global__ void swap_cls_kernel() {
    int idx = blockIdx.x*blockDim.x + threadIdx.x;
    if (idx >= BATCH*64) return;
    int b = idx >> 6, c = idx & 63;
    int m0_ = b*NTOK, m1_ = (b+BATCH)*NTOK;
    size_t i0 = (size_t)m0_*64 + c;
    size_t i1 = (size_t)m1_*64 + c;
    float a = g_X[i0], d = g_X[i1];
    g_X[i0] = d; g_X[i1] = a;
    uint32_t w0 = gword(m0_, c), w1 = gword(m1_, c);
    uint32_t u = g_XNf[w0], v = g_XNf[w1];
    g_XNf[w0] = v; g_XNf[w1] = u;
    uint16_t p = g_XNh[i0], q = g_XNh[i1];
    g_XNh[i0] = q; g_XNh[i1] = p;
}

__global__ void final_kernel(float* __restrict__ out) {
    int idx = blockIdx.x*blockDim.x + threadIdx.x;
    if (idx >= BATCH*64) return;
    int b = idx >> 6, c = idx & 63;
    out[idx] = g_X[(size_t)b*NTOK*64 + c] + g_X[(size_t)(b+BATCH)*NTOK*64 + c];
}

/* ---------------- host ---------------- */
extern "C" void kernel_launch(void* const* d_in, const int* in_sizes, int n_in,
                              void* d_out, int out_size)
{
    const float* hsi       = (const float*)d_in[0];
    const float* lidar     = (const float*)d_in[1];
    const float* cls_hsi   = (const float*)d_in[2];
    const float* cls_lidar = (const float*)d_in[3];
    const float* pos_hsi   = (const float*)d_in[4];
    const float* pos_lidar = (const float*)d_in[5];
    const float* fmg_w     = (const float*)d_in[6];
    const float* ln1_g     = (const float*)d_in[7];
    const float* ln1_b     = (const float*)d_in[8];
    const float* qkv_w     = (const float*)d_in[9];
    const float* out_w     = (const float*)d_in[10];
    const float* out_b     = (const float*)d_in[11];
    const float* ln2_g     = (const float*)d_in[12];
    const float* ln2_b     = (const float*)d_in[13];
    const float* ff_w1     = (const float*)d_in[14];
    const float* ff_b1     = (const float*)d_in[15];
    const float* ff_w2     = (const float*)d_in[16];
    const float* ff_b2     = (const float*)d_in[17];

    float *X;
    uint32_t *XNf, *Wf;
    uint16_t *Qb, *Hb;
    cudaGetSymbolAddress((void**)&X,   g_X);
    cudaGetSymbolAddress((void**)&XNf, g_XNf);
    cudaGetSymbolAddress((void**)&Qb,  g_Q);
    cudaGetSymbolAddress((void**)&Hb,  g_H);
    cudaGetSymbolAddress((void**)&Wf,  g_Wfrag);

    cudaFuncSetAttribute(attn_kernel, cudaFuncAttributeMaxDynamicSharedMemorySize, ATT_BYTES);
    cudaFuncSetAttribute(tgemm<128,128,true,false,true,2,1,false,false>,
                         cudaFuncAttributeMaxDynamicSharedMemorySize, 65536);
    cudaFuncSetAttribute(tgemm<64,64,false,true,true,1,0,true,false>,
                         cudaFuncAttributeMaxDynamicSharedMemorySize, 32768);
    cudaFuncSetAttribute(tgemm<64,64,false,true,true,1,0,true,true>,
                         cudaFuncAttributeMaxDynamicSharedMemorySize, 32768);

    mean_kernel<<<32, 256>>>(hsi, lidar);
    dfm_kernel<<<16, 256>>>(fmg_w);
    build_kernel<<<(M2*DIMC + 255)/256, 256>>>(hsi, cls_hsi, cls_lidar, pos_hsi, pos_lidar);
    ln_frag_kernel<<<M2/8, 256>>>(X, ln1_g, ln1_b);

    prep_qv<<<DEPTH*32768/256, 256>>>(qkv_w);
    prep_gen<<<DEPTH*512*64/256, 256>>>(out_w, 512, 64, OFF_PROJ, DEPTH*512*64);
    prep_gen<<<DEPTH*64*256/256, 256>>>(ff_w1, 64, 256, OFF_FF1, DEPTH*64*256);
    prep_gen<<<DEPTH*256*64/256, 256>>>(ff_w2, 256, 64, OFF_FF2, DEPTH*256*64);

    for (int phase = 0; phase < 2; phase++) {
        for (int L = 0; L < DEPTH; L++) {
            const uint32_t* WL = Wf + (size_t)L*PERL;
            int Ln = (L + 1) & 3;
            /* fused QV + attention */
            attn_kernel<<<1024, 512, ATT_BYTES>>>(WL + OFF_QV);
            /* proj + residual + fused LN2 -> XNf only */
            tgemm<64,64,false,true,true,1,0,true,false><<<dim3(1,452), 256, 32768>>>(
                Qb, WL + OFF_PROJ, out_b + L*64, X,
                ln2_g + L*64, ln2_b + L*64, 512, 512, 64, 64);
            /* ff1 (A = XNf frag) + GELU -> H bf16 */
            tgemm<128,128,true,false,true,2,1,false,false><<<dim3(2,226), 256, 65536>>>(
                XNf, WL + OFF_FF1, ff_b1 + L*256, Hb,
                nullptr, nullptr, 64, 0, 256, 256);
            /* ff2 + residual + fused LN1(next) -> XNf + XNh */
            tgemm<64,64,false,true,true,1,0,true,true><<<dim3(1,452), 256, 32768>>>(
                Hb, WL + OFF_FF2, ff_b2 + L*64, X,
                ln1_g + Ln*64, ln1_b + Ln*64, 256, 256, 64, 64);
        }
        if (phase == 0) swap_cls_kernel<<<16, 256>>>();
    }
    final_kernel<<<16, 256>>>((float*)d_out);
}

// round 14
// speedup vs baseline: 1.3521x; 1.0886x over previous
#include <cuda_runtime.h>
#include <cuda_bf16.h>
#include <math.h>
#include <cstdint>

#define BATCH   64
#define DIMC    64
#define HEADS   8
#define DHEAD   64
#define INNER   512
#define MLPD    256
#define DEPTH   4
#define NPATCH  225
#define NTOK    226
#define M2      (2*BATCH*NTOK)   /* 28928 rows */
#define MBTOT   (M2/16)          /* 1808 m-blocks */
#define EPSV    1e-5f
#define SCALEV  0.125f

/* ---------------- mma helpers ---------------- */
__device__ __forceinline__ uint32_t smem_u32(const void* p) {
    uint32_t a;
    asm("{ .reg .u64 t; cvta.to.shared.u64 t, %1; cvt.u32.u64 %0, t; }" : "=r"(a) : "l"(p));
    return a;
}
__device__ __forceinline__ void mma_bf16(float* c, const uint32_t* a, const uint32_t* b) {
    asm volatile("mma.sync.aligned.m16n8k16.row.col.f32.bf16.bf16.f32 "
        "{%0,%1,%2,%3}, {%4,%5,%6,%7}, {%8,%9}, {%0,%1,%2,%3};"
        : "+f"(c[0]), "+f"(c[1]), "+f"(c[2]), "+f"(c[3])
        : "r"(a[0]), "r"(a[1]), "r"(a[2]), "r"(a[3]), "r"(b[0]), "r"(b[1]));
}
__device__ __forceinline__ void mma_tf32(float* c, const uint32_t* a, const uint32_t* b) {
    asm volatile("mma.sync.aligned.m16n8k8.row.col.f32.tf32.tf32.f32 "
        "{%0,%1,%2,%3}, {%4,%5,%6,%7}, {%8,%9}, {%0,%1,%2,%3};"
        : "+f"(c[0]), "+f"(c[1]), "+f"(c[2]), "+f"(c[3])
        : "r"(a[0]), "r"(a[1]), "r"(a[2]), "r"(a[3]), "r"(b[0]), "r"(b[1]));
}
__device__ __forceinline__ void ldm_x4_trans(uint32_t* r, uint32_t addr) {
    asm volatile("ldmatrix.sync.aligned.m8n8.x4.trans.shared.b16 {%0,%1,%2,%3}, [%4];"
        : "=r"(r[0]), "=r"(r[1]), "=r"(r[2]), "=r"(r[3]) : "r"(addr));
}
__device__ __forceinline__ uint32_t totf(float x) {
    uint32_t r; asm("cvt.rna.tf32.f32 %0, %1;" : "=r"(r) : "f"(x)); return r;
}
#define PACKBF(r, lo_, hi_) asm("cvt.rn.bf16x2.f32 %0, %1, %2;" : "=r"(r) : "f"(hi_), "f"(lo_))
#define GELU1(x) (0.5f*(x)*(1.0f + erff((x)*0.70710678118654752f)))

/* tf32 fragment-layout word index (verified R5/R7) */
__host__ __device__ inline int faddr(int k, int n, int npairs) {
    return ((k>>3)*npairs + (n>>4))*128 + ((n&7)*4 + (k&3))*4 + (((n>>3)&1)*2) + ((k>>2)&1);
}
/* A-fragment word index in global XNf (m rows over MBTOT blocks) */
__device__ __forceinline__ uint32_t gword(int m, int k) {
    return (uint32_t)(((k>>3)*MBTOT + (m>>4))*128 + (m&7)*16 + ((m>>3)&1) + ((k>>2)&1)*2 + (k&3)*4);
}

/* ---------------- scratch ---------------- */
__device__ float    g_X  [(size_t)M2*DIMC];
__device__ uint32_t g_XNf[(size_t)M2*DIMC];   /* LN output, tf32 frag-order */
__device__ uint16_t g_XNh[(size_t)M2*DIMC];   /* LN output, bf16 row-major  */
__device__ uint16_t g_Q [(size_t)M2*INNER];   /* attn O output (bf16), proj A */
__device__ float    g_sdfm[BATCH*DIMC];
__device__ float    g_xmean[BATCH*2*DIMC];
/* per layer: QV bf16-frag @0 (32768), proj tf32 @32768 (32768),
   ff1 tf32 @65536 (16384), ff2 bf16-frag @81920 (8192) */
#define PERL     98304
#define OFF_QV   0
#define OFF_PROJ 32768
#define OFF_FF1  65536
#define OFF_FF2  81920
__device__ uint32_t g_Wfrag[(size_t)DEPTH*PERL];

/* ---------------- prologue ---------------- */
__global__ void mean_kernel(const float* __restrict__ hsi, const float* __restrict__ lidar) {
    int idx = blockIdx.x*blockDim.x + threadIdx.x;
    if (idx >= BATCH*128) return;
    int b = idx >> 7, c = idx & 127;
    const float* src = (c < 64) ? (hsi + ((size_t)b*64 + c)*NPATCH)
                                : (lidar + ((size_t)b*64 + (c-64))*NPATCH);
    float s = 0.f;
    for (int p = 0; p < NPATCH; p++) s += src[p];
    g_xmean[idx] = s * (1.0f/NPATCH);
}

__global__ void dfm_kernel(const float* __restrict__ fmg_w) {
    int idx = blockIdx.x*blockDim.x + threadIdx.x;
    if (idx >= BATCH*64) return;
    int b = idx >> 6, d = idx & 63;
    const float* xm = g_xmean + b*128;
    const float* wc = fmg_w + d*65;
    float s = 0.f;
    for (int c = 0; c < 128; c++) s += xm[c] * wc[(size_t)c*4096];
    float sig = 1.0f/(1.0f + expf(-s));
    g_sdfm[idx] = sqrtf(sig * SCALEV);
}

__global__ void build_kernel(const float* __restrict__ hsi,
                             const float* __restrict__ cls_hsi, const float* __restrict__ cls_lidar,
                             const float* __restrict__ pos_hsi, const float* __restrict__ pos_lidar) {
    int idx = blockIdx.x*blockDim.x + threadIdx.x;
    if (idx >= M2*DIMC) return;
    int c  = idx & 63;
    int n  = (idx >> 6) % NTOK;
    int bp = idx / (NTOK*64);
    int b  = bp & 63;
    int br = bp >> 6;
    const float* cls = br ? cls_lidar : cls_hsi;
    const float* pos = br ? pos_lidar : pos_hsi;
    float v = (n == 0) ? cls[c] : hsi[((size_t)b*64 + c)*NPATCH + (n-1)];
    g_X[idx] = v + pos[n*64 + c];
}

/* ---------------- layernorm -> XNf (tf32 frag) + XNh (bf16 rows) ---------------- */
__global__ void ln_frag_kernel(const float* __restrict__ Xp,
                               const float* __restrict__ g, const float* __restrict__ bb) {
    int w = threadIdx.x >> 5, lane = threadIdx.x & 31;
    int row = blockIdx.x*8 + w;
    const float* xr = Xp + (size_t)row*64;
    float x0 = xr[lane], x1 = xr[lane+32];
    float s = x0 + x1;
    #pragma unroll
    for (int o = 16; o; o >>= 1) s += __shfl_xor_sync(0xffffffffu, s, o);
    float m = s * (1.0f/64.0f);
    float d0 = x0 - m, d1 = x1 - m;
    float v = d0*d0 + d1*d1;
    #pragma unroll
    for (int o = 16; o; o >>= 1) v += __shfl_xor_sync(0xffffffffu, v, o);
    float r = rsqrtf(v*(1.0f/64.0f) + EPSV);
    float y0 = d0*r*g[lane]    + bb[lane];
    float y1 = d1*r*g[lane+32] + bb[lane+32];
    g_XNf[gword(row, lane)]    = totf(y0);
    g_XNf[gword(row, lane+32)] = totf(y1);
    __nv_bfloat16 h0 = __float2bfloat16(y0), h1 = __float2bfloat16(y1);
    g_XNh[(size_t)row*64 + lane]      = *(uint16_t*)&h0;
    g_XNh[(size_t)row*64 + lane + 32] = *(uint16_t*)&h1;
}

/* ---------------- weight prep ---------------- */
__global__ void prep_qv(const float* __restrict__ qkv_w) {
    int idx = blockIdx.x*blockDim.x + threadIdx.x;
    if (idx >= DEPTH*32768) return;
    int h_ = idx & 1;
    int l  = (idx >> 1) & 31;
    int j  = (idx >> 6) & 127;
    int kb = (idx >> 13) & 3;
    int L  = idx >> 15;
    int k = kb*16 + (l & 3)*2 + h_*8;
    int n = j*8 + (l >> 2);
    int col = (n < 512) ? n : n + 512;
    const float* wp = qkv_w + (size_t)L*64*1536;
    float w0 = wp[(size_t)k*1536 + col];
    float w1 = wp[(size_t)(k+1)*1536 + col];
    uint32_t pk; PACKBF(pk, w0, w1);
    g_Wfrag[(size_t)L*PERL + OFF_QV + idx % 32768] = pk;
}
/* ff2 [256,64] -> bf16 B-frag layout: 16 kb x 8 j x 32 lane x 2 halves = 8192 words/layer */
__global__ void prep_w2bf(const float* __restrict__ ff_w2) {
    int idx = blockIdx.x*blockDim.x + threadIdx.x;
    if (idx >= DEPTH*8192) return;
    int h_ = idx & 1;
    int l  = (idx >> 1) & 31;
    int j  = (idx >> 6) & 7;
    int kb = (idx >> 9) & 15;
    int L  = idx >> 13;
    int k = kb*16 + (l & 3)*2 + h_*8;
    int n = j*8 + (l >> 2);
    const float* wp = ff_w2 + (size_t)L*256*64;
    float w0 = wp[(size_t)k*64 + n];
    float w1 = wp[(size_t)(k+1)*64 + n];
    uint32_t pk; PACKBF(pk, w0, w1);
    g_Wfrag[(size_t)L*PERL + OFF_FF2 + idx % 8192] = pk;
}
__global__ void prep_gen(const float* __restrict__ w, int K, int N, int dstoff, int total) {
    int idx = blockIdx.x*blockDim.x + threadIdx.x;
    if (idx >= total) return;
    int kn = K*N;
    int L = idx / kn, rem = idx % kn;
    int k = rem / N, n = rem % N;
    g_Wfrag[(size_t)L*PERL + dstoff + faddr(k, n, N >> 4)] = totf(w[(size_t)idx]);
}

/* ---------------- tf32 mma GEMM (proj only now) ---------------- */
template<int BM, int BN, bool GELU_, bool ACC_, bool BIAS_, int AIN, int OUT, bool LNOUT, bool XNH_>
__global__ void __launch_bounds__(256) tgemm(
    const void* __restrict__ Ap, const uint32_t* __restrict__ Bf,
    const float* __restrict__ bias, void* __restrict__ Cp_,
    const float* __restrict__ lngamma, const float* __restrict__ lnbeta,
    int K, int lda, int Ntot, int ldc)
{
    constexpr int MBLKS = BM/16;
    constexpr int NPB   = BN/16;
    constexpr int MF    = BM/64;
    constexpr int WN    = BN/2;
    constexpr int NF    = WN/8;
    const int NPAIRS = Ntot >> 4;

    extern __shared__ uint32_t dsm[];
    uint32_t* Asm = dsm;
    uint32_t* Bsm = dsm + 8*MBLKS*128;

    int t = threadIdx.x, lane = t & 31, w = t >> 5;
    int wm = w & 3, wn = w >> 2;
    int m0 = blockIdx.y * BM;
    int n0 = blockIdx.x * BN;
    int np0 = n0 >> 4;

    float acc[MF][NF][4];
    #pragma unroll
    for (int i = 0; i < MF; i++)
        #pragma unroll
        for (int j = 0; j < NF; j++)
            #pragma unroll
            for (int q = 0; q < 4; q++) acc[i][j][q] = 0.f;

    for (int kt = 0; kt < K; kt += 64) {
        if (AIN == 1) {
            #pragma unroll
            for (int it = 0; it < BM/32; it++) {
                int idx = t + it*256;
                int m = idx >> 3, k8 = (idx & 7)*8;
                uint4 v = *(const uint4*)((const uint16_t*)Ap + (size_t)(m0+m)*lda + kt + k8);
                const uint16_t* hp = (const uint16_t*)&v;
                int base = ((k8>>3)*MBLKS + (m>>4))*128 + (m&7)*16 + ((m>>3)&1);
                #pragma unroll
                for (int j = 0; j < 8; j++)
                    Asm[base + (j>>2)*2 + (j&3)*4] = ((uint32_t)hp[j]) << 16;
            }
        } else {
            const uint4* Afr = (const uint4*)Ap;
            int mb0 = m0 >> 4;
            #pragma unroll
            for (int it = 0; it < MBLKS; it++) {
                int i = t + it*256;
                int kc = i / (MBLKS*32);
                int rem = i % (MBLKS*32);
                ((uint4*)Asm)[i] = __ldg(Afr + (size_t)(kc*MBTOT + mb0 + (rem>>5))*32 + (rem&31));
            }
        }
        int kc0 = kt >> 3;
        #pragma unroll
        for (int it = 0; it < NPB; it++) {
            int i = t + it*256;
            int kc = i / (NPB*32);
            int rem = i % (NPB*32);
            int np = rem >> 5, l4 = rem & 31;
            ((uint4*)Bsm)[i] = __ldg((const uint4*)(Bf + (size_t)((kc0+kc)*NPAIRS + np0 + np)*128 + l4*4));
        }
        __syncthreads();

        #pragma unroll
        for (int kc = 0; kc < 8; kc++) {
            uint32_t af[MF][4];
            #pragma unroll
            for (int mf = 0; mf < MF; mf++)
                *(uint4*)af[mf] = *(const uint4*)&Asm[(kc*MBLKS + wm*MF + mf)*128 + lane*4];
            #pragma unroll
            for (int np = 0; np < NF/2; np++) {
                uint4 bv = *(const uint4*)&Bsm[(kc*NPB + wn*(NF/2) + np)*128 + lane*4];
                uint32_t* bf = (uint32_t*)&bv;
                #pragma unroll
                for (int mf = 0; mf < MF; mf++) {
                    mma_tf32(acc[mf][2*np],   af[mf], bf);
                    mma_tf32(acc[mf][2*np+1], af[mf], bf + 2);
                }
            }
        }
        __syncthreads();
    }

    float* rowbuf = (float*)dsm;
    int r = lane >> 2, c2 = (lane & 3)*2;
    #pragma unroll
    for (int mf = 0; mf < MF; mf++) {
        int mrow = m0 + wm*(MF*16) + mf*16 + r;
        #pragma unroll
        for (int nf = 0; nf < NF; nf++) {
            int nout = n0 + wn*WN + nf*8 + c2;
            float v00 = acc[mf][nf][0], v01 = acc[mf][nf][1];
            float v10 = acc[mf][nf][2], v11 = acc[mf][nf][3];
            if (BIAS_) {
                float2 bb = *(const float2*)&bias[nout];
                v00 += bb.x; v01 += bb.y; v10 += bb.x; v11 += bb.y;
            }
            if (GELU_) { v00 = GELU1(v00); v01 = GELU1(v01); v10 = GELU1(v10); v11 = GELU1(v11); }
            if (OUT == 1) {
                uint16_t* dst = (uint16_t*)Cp_;
                uint32_t pk0, pk1;
                PACKBF(pk0, v00, v01);
                PACKBF(pk1, v10, v11);
                *(uint32_t*)(dst + (size_t)mrow*ldc + nout)     = pk0;
                *(uint32_t*)(dst + (size_t)(mrow+8)*ldc + nout) = pk1;
            } else {
                float* dst = (float*)Cp_;
                float* p0 = dst + (size_t)mrow*ldc + nout;
                float* p1 = dst + (size_t)(mrow+8)*ldc + nout;
                if (ACC_) {
                    float2 o0 = *(float2*)p0, o1 = *(float2*)p1;
                    v00 += o0.x; v01 += o0.y; v10 += o1.x; v11 += o1.y;
                }
                float2 s0; s0.x = v00; s0.y = v01;
                float2 s1; s1.x = v10; s1.y = v11;
                *(float2*)p0 = s0;
                *(float2*)p1 = s1;
                if (LNOUT) {
                    int mr0 = mrow - m0, mr1 = mr0 + 8;
                    rowbuf[mr0*66 + nout]     = v00;
                    rowbuf[mr0*66 + nout + 1] = v01;
                    rowbuf[mr1*66 + nout]     = v10;
                    rowbuf[mr1*66 + nout + 1] = v11;
                }
            }
        }
    }

    if (LNOUT) {
        __syncthreads();
        float lg0 = lngamma[lane], lg1 = lngamma[lane+32];
        float lb0 = lnbeta[lane],  lb1 = lnbeta[lane+32];
        #pragma unroll 1
        for (int i = 0; i < BM/8; i++) {
            int rr = w*(BM/8) + i;
            float x0 = rowbuf[rr*66 + lane], x1 = rowbuf[rr*66 + lane + 32];
            float s = x0 + x1;
            #pragma unroll
            for (int o = 16; o; o >>= 1) s += __shfl_xor_sync(0xffffffffu, s, o);
            float mean = s * (1.0f/64.0f);
            float d0 = x0 - mean, d1 = x1 - mean;
            float vv = d0*d0 + d1*d1;
            #pragma unroll
            for (int o = 16; o; o >>= 1) vv += __shfl_xor_sync(0xffffffffu, vv, o);
            float ri = rsqrtf(vv*(1.0f/64.0f) + EPSV);
            int m = m0 + rr;
            float y0 = d0*ri*lg0 + lb0;
            float y1 = d1*ri*lg1 + lb1;
            g_XNf[gword(m, lane)]    = totf(y0);
            g_XNf[gword(m, lane+32)] = totf(y1);
            if (XNH_) {
                __nv_bfloat16 h0 = __float2bfloat16(y0), h1 = __float2bfloat16(y1);
                g_XNh[(size_t)m*64 + lane]      = *(uint16_t*)&h0;
                g_XNh[(size_t)m*64 + lane + 32] = *(uint16_t*)&h1;
            }
        }
    }
}

/* ---------------- fused FF1+FF2 kernel ----------------
   512 threads, 128 rows per CTA (grid 226).
   GEMM1: tf32, A = XNf frag (bulk copy), B = W1 frag staged in smem, GELU ->
   H bf16 in smem (stride 264, conflict-free). GEMM2: bf16 mma, A = H smem,
   B = W2 bf16-frag via __ldg. Epilogue: X += out (+bias), fused LN1(next)
   -> XNf + XNh. */
#define FF_ASM   0          /* 32768B: XNf tile / later unused            */
#define FF_B1    32768      /* 65536B: W1 frags / later rowbuf (33792B)   */
#define FF_H     98304      /* 67584B: H bf16 128 x 264                   */
#define FF_BYTES 165888
#define HSTR     264

__global__ void __launch_bounds__(512) ff_kernel(
    const uint32_t* __restrict__ XNfp, const uint32_t* __restrict__ W1f,
    const uint32_t* __restrict__ W2f,
    const float* __restrict__ b1, const float* __restrict__ b2,
    float* __restrict__ Xp,
    const float* __restrict__ lngamma, const float* __restrict__ lnbeta)
{
    extern __shared__ char smc[];
    uint32_t* Asm = (uint32_t*)(smc + FF_ASM);
    uint32_t* Bsm = (uint32_t*)(smc + FF_B1);
    uint16_t* Hsm = (uint16_t*)(smc + FF_H);

    int t = threadIdx.x, lane = t & 31, w = t >> 5;
    int wm = w & 3, wn = w >> 2;          /* 4 m-warps x 4 n-warps */
    int m0 = blockIdx.x * 128;
    int mb0 = m0 >> 4;
    int r = lane >> 2, c2 = (lane & 3)*2;

    /* stage A (XNf frag, 8 mblks) and B1 (W1 frag, 16 npairs) */
    #pragma unroll
    for (int it = 0; it < 4; it++) {
        int i = t + it*512;
        int kc = i >> 8, rem = i & 255;
        ((uint4*)Asm)[i] = __ldg((const uint4*)XNfp + (size_t)(kc*MBTOT + mb0 + (rem>>5))*32 + (rem&31));
    }
    #pragma unroll
    for (int it = 0; it < 8; it++) {
        int i = t + it*512;
        int kc = i >> 9, rem = i & 511;
        ((uint4*)Bsm)[i] = __ldg((const uint4*)W1f + (size_t)(kc*16 + (rem>>5))*32 + (rem&31));
    }
    __syncthreads();

    /* ---- GEMM1: [128 x 256] = XN[128x64] @ W1, tf32 ---- */
    {
        float acc[2][8][4];
        #pragma unroll
        for (int i = 0; i < 2; i++)
            #pragma unroll
            for (int j = 0; j < 8; j++)
                #pragma unroll
                for (int q = 0; q < 4; q++) acc[i][j][q] = 0.f;

        #pragma unroll
        for (int kc = 0; kc < 8; kc++) {
            uint32_t af[2][4];
            #pragma unroll
            for (int mf = 0; mf < 2; mf++)
                *(uint4*)af[mf] = *(const uint4*)&Asm[(kc*8 + wm*2 + mf)*128 + lane*4];
            #pragma unroll
            for (int nb = 0; nb < 4; nb++) {
                uint4 bv = *(const uint4*)&Bsm[(kc*16 + wn*4 + nb)*128 + lane*4];
                uint32_t* bf = (uint32_t*)&bv;
                #pragma unroll
                for (int mf = 0; mf < 2; mf++) {
                    mma_tf32(acc[mf][2*nb],   af[mf], bf);
                    mma_tf32(acc[mf][2*nb+1], af[mf], bf + 2);
                }
            }
        }
        /* epilogue1: bias + GELU -> Hsm bf16 */
        #pragma unroll
        for (int mf = 0; mf < 2; mf++) {
            int row0 = wm*32 + mf*16 + r;
            #pragma unroll
            for (int nf = 0; nf < 8; nf++) {
                int col = wn*64 + nf*8 + c2;
                float2 bb = *(const float2*)&b1[col];
                float v00 = GELU1(acc[mf][nf][0] + bb.x);
                float v01 = GELU1(acc[mf][nf][1] + bb.y);
                float v10 = GELU1(acc[mf][nf][2] + bb.x);
                float v11 = GELU1(acc[mf][nf][3] + bb.y);
                uint32_t pk0, pk1;
                PACKBF(pk0, v00, v01);
                PACKBF(pk1, v10, v11);
                *(uint32_t*)&Hsm[row0*HSTR + col]       = pk0;
                *(uint32_t*)&Hsm[(row0 + 8)*HSTR + col] = pk1;
            }
        }
    }
    __syncthreads();

    /* ---- GEMM2: [128 x 64] = H[128x256] @ W2, bf16 ---- */
    float acc2[2][2][4];
    #pragma unroll
    for (int i = 0; i < 2; i++)
        #pragma unroll
        for (int j = 0; j < 2; j++)
            #pragma unroll
            for (int q = 0; q < 4; q++) acc2[i][j][q] = 0.f;

    #pragma unroll
    for (int kb = 0; kb < 16; kb++) {
        uint32_t af[2][4];
        #pragma unroll
        for (int mf = 0; mf < 2; mf++) {
            const uint16_t* hrow = Hsm + (wm*32 + mf*16 + r)*HSTR + kb*16 + c2;
            af[mf][0] = *(const uint32_t*)(hrow);
            af[mf][1] = *(const uint32_t*)(hrow + 8*HSTR);
            af[mf][2] = *(const uint32_t*)(hrow + 8);
            af[mf][3] = *(const uint32_t*)(hrow + 8*HSTR + 8);
        }
        #pragma unroll
        for (int nj = 0; nj < 2; nj++) {
            int j = wn*2 + nj;
            uint2 bw = __ldg((const uint2*)(W2f + (size_t)((kb*8 + j)*32 + lane)*2));
            #pragma unroll
            for (int mf = 0; mf < 2; mf++)
                mma_bf16(acc2[mf][nj], af[mf], (const uint32_t*)&bw);
        }
    }

    /* epilogue2: residual + bias -> X, rowbuf for LN */
    float* rowbuf = (float*)(smc + FF_B1);
    #pragma unroll
    for (int mf = 0; mf < 2; mf++) {
        int mrow = m0 + wm*32 + mf*16 + r;
        int mr0 = mrow - m0;
        #pragma unroll
        for (int nj = 0; nj < 2; nj++) {
            int nout = wn*16 + nj*8 + c2;
            float2 bb = *(const float2*)&b2[nout];
            float v00 = acc2[mf][nj][0] + bb.x, v01 = acc2[mf][nj][1] + bb.y;
            float v10 = acc2[mf][nj][2] + bb.x, v11 = acc2[mf][nj][3] + bb.y;
            float* p0 = Xp + (size_t)mrow*64 + nout;
            float* p1 = Xp + (size_t)(mrow+8)*64 + nout;
            float2 o0 = *(float2*)p0, o1 = *(float2*)p1;
            v00 += o0.x; v01 += o0.y; v10 += o1.x; v11 += o1.y;
            float2 s0; s0.x = v00; s0.y = v01;
            float2 s1; s1.x = v10; s1.y = v11;
            *(float2*)p0 = s0;
            *(float2*)p1 = s1;
            rowbuf[mr0*66 + nout]       = v00;
            rowbuf[mr0*66 + nout + 1]   = v01;
            rowbuf[(mr0+8)*66 + nout]   = v10;
            rowbuf[(mr0+8)*66 + nout+1] = v11;
        }
    }
    __syncthreads();

    /* fused LN1(next layer) -> XNf + XNh */
    {
        float lg0 = lngamma[lane], lg1 = lngamma[lane+32];
        float lb0 = lnbeta[lane],  lb1 = lnbeta[lane+32];
        #pragma unroll 1
        for (int i = 0; i < 8; i++) {
            int rr = w*8 + i;
            float x0 = rowbuf[rr*66 + lane], x1 = rowbuf[rr*66 + lane + 32];
            float s = x0 + x1;
            #pragma unroll
            for (int o = 16; o; o >>= 1) s += __shfl_xor_sync(0xffffffffu, s, o);
            float mean = s * (1.0f/64.0f);
            float d0 = x0 - mean, d1 = x1 - mean;
            float vv = d0*d0 + d1*d1;
            #pragma unroll
            for (int o = 16; o; o >>= 1) vv += __shfl_xor_sync(0xffffffffu, vv, o);
            float ri = rsqrtf(vv*(1.0f/64.0f) + EPSV);
            int m = m0 + rr;
            float y0 = d0*ri*lg0 + lb0;
            float y1 = d1*ri*lg1 + lb1;
            g_XNf[gword(m, lane)]    = totf(y0);
            g_XNf[gword(m, lane+32)] = totf(y1);
            __nv_bfloat16 h0 = __float2bfloat16(y0), h1 = __float2bfloat16(y1);
            g_XNh[(size_t)m*64 + lane]      = *(uint16_t*)&h0;
            g_XNh[(size_t)m*64 + lane + 32] = *(uint16_t*)&h1;
        }
    }
}

/* ---------------- fused QV + attention (unchanged from R13) ---------------- */
#define XSTRIDE 72
#define XBUF    36864
#define ATT_BYTES (3*XBUF)

__global__ void __launch_bounds__(512) attn_kernel(const uint32_t* __restrict__ Wqv) {
    extern __shared__ char smc[];
    uint16_t* Xh = (uint16_t*)smc;
    uint16_t* Qh = (uint16_t*)(smc + XBUF);
    uint16_t* Vh = (uint16_t*)(smc + 2*XBUF);
    uint32_t vbase = smem_u32(smc) + 2*XBUF;

    int t = threadIdx.x;
    int bh = blockIdx.x;
    int bp = bh >> 3, h = bh & 7;
    int bidx = bp & 63;
    uint16_t* Ob = g_Q + (size_t)bp*NTOK*INNER + h*DHEAD;
    const uint16_t* Xg = g_XNh + (size_t)bp*NTOK*64;

    for (int f = t; f < NTOK*8; f += 512) {
        int n = f >> 3, d8 = (f & 7)*8;
        *(uint4*)&Xh[n*XSTRIDE + d8] = *(const uint4*)(Xg + (size_t)n*64 + d8);
    }
    if (t < 270) ((uint4*)(Xh + NTOK*XSTRIDE))[t] = make_uint4(0,0,0,0);
    __syncthreads();

    int lane = t & 31, wid = t >> 5;
    int m0 = wid*16, r = lane >> 2, c2 = (lane & 3)*2;

    {
        uint32_t xa[4][4];
        #pragma unroll
        for (int kb = 0; kb < 4; kb++) {
            const uint16_t* xrow = Xh + (m0 + r)*XSTRIDE + kb*16 + c2;
            xa[kb][0] = *(const uint32_t*)(xrow);
            xa[kb][1] = *(const uint32_t*)(xrow + 8*XSTRIDE);
            xa[kb][2] = *(const uint32_t*)(xrow + 8);
            xa[kb][3] = *(const uint32_t*)(xrow + 8*XSTRIDE + 8);
        }
        float qc[8][4];
        #pragma unroll
        for (int j = 0; j < 8; j++)
            #pragma unroll
            for (int q = 0; q < 4; q++) qc[j][q] = 0.f;
        #pragma unroll
        for (int kb = 0; kb < 4; kb++)
            #pragma unroll
            for (int j = 0; j < 8; j++) {
                uint2 bw = __ldg((const uint2*)(Wqv + (size_t)(((kb*128) + h*8 + j)*32 + lane)*2));
                mma_bf16(qc[j], xa[kb], (const uint32_t*)&bw);
            }
        #pragma unroll
        for (int j = 0; j < 8; j++) {
            int d = j*8 + c2;
            float2 sd = *(const float2*)&g_sdfm[bidx*64 + d];
            uint32_t p0, p1;
            PACKBF(p0, qc[j][0]*sd.x, qc[j][1]*sd.y);
            PACKBF(p1, qc[j][2]*sd.x, qc[j][3]*sd.y);
            *(uint32_t*)&Qh[(m0 + r)*XSTRIDE + d]     = p0;
            *(uint32_t*)&Qh[(m0 + r + 8)*XSTRIDE + d] = p1;
        }
        float vc[8][4];
        #pragma unroll
        for (int j = 0; j < 8; j++)
            #pragma unroll
            for (int q = 0; q < 4; q++) vc[j][q] = 0.f;
        #pragma unroll
        for (int kb = 0; kb < 4; kb++)
            #pragma unroll
            for (int j = 0; j < 8; j++) {
                uint2 bw = __ldg((const uint2*)(Wqv + (size_t)(((kb*128) + 64 + h*8 + j)*32 + lane)*2));
                mma_bf16(vc[j], xa[kb], (const uint32_t*)&bw);
            }
        #pragma unroll
        for (int j = 0; j < 8; j++) {
            int d = j*8 + c2;
            uint32_t p0, p1;
            PACKBF(p0, vc[j][0], vc[j][1]);
            PACKBF(p1, vc[j][2], vc[j][3]);
            *(uint32_t*)&Vh[(m0 + r)*XSTRIDE + d]     = p0;
            *(uint32_t*)&Vh[(m0 + r + 8)*XSTRIDE + d] = p1;
        }
    }
    __syncthreads();

    uint32_t qa[4][4];
    #pragma unroll
    for (int kb = 0; kb < 4; kb++) {
        const uint16_t* qrow = Qh + (m0 + r)*XSTRIDE + kb*16 + c2;
        qa[kb][0] = *(const uint32_t*)(qrow);
        qa[kb][1] = *(const uint32_t*)(qrow + 8*XSTRIDE);
        qa[kb][2] = *(const uint32_t*)(qrow + 8);
        qa[kb][3] = *(const uint32_t*)(qrow + 8*XSTRIDE + 8);
    }

    float O[8][4];
    #pragma unroll
    for (int nt = 0; nt < 8; nt++)
        #pragma unroll
        for (int j = 0; j < 4; j++) O[nt][j] = 0.f;
    float rs0 = 0.f, rs1 = 0.f;

    for (int ch = 0; ch < 4; ch++) {
        float S[8][4];
        #pragma unroll
        for (int nt = 0; nt < 8; nt++)
            #pragma unroll
            for (int j = 0; j < 4; j++) S[nt][j] = 0.f;
        #pragma unroll
        for (int kb = 0; kb < 4; kb++) {
            #pragma unroll
            for (int nt = 0; nt < 8; nt++) {
                const uint16_t* brow = Qh + (ch*64 + nt*8 + r)*XSTRIDE + kb*16 + c2;
                uint32_t b[2] = { *(const uint32_t*)brow, *(const uint32_t*)(brow + 8) };
                mma_bf16(S[nt], qa[kb], b);
            }
        }
        uint32_t pa[4][4];
        #pragma unroll
        for (int nt = 0; nt < 8; nt++) {
            int col = ch*64 + nt*8 + c2;
            float e0 = (col     < NTOK) ? __expf(S[nt][0]) : 0.f;
            float e1 = (col + 1 < NTOK) ? __expf(S[nt][1]) : 0.f;
            float e2 = (col     < NTOK) ? __expf(S[nt][2]) : 0.f;
            float e3 = (col + 1 < NTOK) ? __expf(S[nt][3]) : 0.f;
            rs0 += e0 + e1;
            rs1 += e2 + e3;
            uint32_t plo, phi;
            PACKBF(plo, e0, e1);
            PACKBF(phi, e2, e3);
            pa[nt >> 1][(nt & 1)*2]     = plo;
            pa[nt >> 1][(nt & 1)*2 + 1] = phi;
        }
        #pragma unroll
        for (int kb = 0; kb < 4; kb++) {
            uint32_t vb[16];
            int krow = ch*64 + kb*16 + (lane & 15);
            int coff = 8*(lane >> 4);
            #pragma unroll
            for (int q = 0; q < 4; q++)
                ldm_x4_trans(vb + q*4, vbase + (uint32_t)(krow*XSTRIDE + q*16 + coff)*2);
            #pragma unroll
            for (int nt = 0; nt < 8; nt++)
                mma_bf16(O[nt], pa[kb], &vb[(nt >> 1)*4 + (nt & 1)*2]);
        }
    }

    #pragma unroll
    for (int o = 1; o <= 2; o <<= 1) {
        rs0 += __shfl_xor_sync(0xffffffffu, rs0, o);
        rs1 += __shfl_xor_sync(0xffffffffu, rs1, o);
    }
    float ri0 = 1.0f/rs0, ri1 = 1.0f/rs1;
    int i0 = m0 + r;
    if (i0 < NTOK) {
        uint16_t* op = Ob + (size_t)i0*INNER;
        #pragma unroll
        for (int nt = 0; nt < 8; nt++) {
            uint32_t pk;
            PACKBF(pk, O[nt][0]*ri0, O[nt][1]*ri0);
            *(uint32_t*)(op + nt*8 + c2) = pk;
        }
    }
    if (i0 + 8 < NTOK) {
        uint16_t* op = Ob + (size_t)(i0 + 8)*INNER;
        #pragma unroll
        for (int nt = 0; nt < 8; nt++) {
            uint32_t pk;
            PACKBF(pk, O[nt][2]*ri1, O[nt][3]*ri1);
            *(uint32_t*)(op + nt*8 + c2) = pk;
        }
    }
}

/* ---------------- token exchange (X + XNf + XNh) + final ---------------- */
__global__ void swap_cls_kernel() {
    int idx = blockIdx.x*blockDim.x + threadIdx.x;
    if (idx >= BATCH*64) return;
    int b = idx >> 6, c = idx & 63;
    int m0_ = b*NTOK, m1_ = (b+BATCH)*NTOK;
    size_t i0 = (size_t)m0_*64 + c;
    size_t i1 = (size_t)m1_*64 + c;
    float a = g_X[i0], d = g_X[i1];
    g_X[i0] = d; g_X[i1] = a;
    uint32_t w0 = gword(m0_, c), w1 = gword(m1_, c);
    uint32_t u = g_XNf[w0], v = g_XNf[w1];
    g_XNf[w0] = v; g_XNf[w1] = u;
    uint16_t p = g_XNh[i0], q = g_XNh[i1];
    g_XNh[i0] = q; g_XNh[i1] = p;
}

__global__ void final_kernel(float* __restrict__ out) {
    int idx = blockIdx.x*blockDim.x + threadIdx.x;
    if (idx >= BATCH*64) return;
    int b = idx >> 6, c = idx & 63;
    out[idx] = g_X[(size_t)b*NTOK*64 + c] + g_X[(size_t)(b+BATCH)*NTOK*64 + c];
}

/* ---------------- host ---------------- */
extern "C" void kernel_launch(void* const* d_in, const int* in_sizes, int n_in,
                              void* d_out, int out_size)
{
    const float* hsi       = (const float*)d_in[0];
    const float* lidar     = (const float*)d_in[1];
    const float* cls_hsi   = (const float*)d_in[2];
    const float* cls_lidar = (const float*)d_in[3];
    const float* pos_hsi   = (const float*)d_in[4];
    const float* pos_lidar = (const float*)d_in[5];
    const float* fmg_w     = (const float*)d_in[6];
    const float* ln1_g     = (const float*)d_in[7];
    const float* ln1_b     = (const float*)d_in[8];
    const float* qkv_w     = (const float*)d_in[9];
    const float* out_w     = (const float*)d_in[10];
    const float* out_b     = (const float*)d_in[11];
    const float* ln2_g     = (const float*)d_in[12];
    const float* ln2_b     = (const float*)d_in[13];
    const float* ff_w1     = (const float*)d_in[14];
    const float* ff_b1     = (const float*)d_in[15];
    const float* ff_w2     = (const float*)d_in[16];
    const float* ff_b2     = (const float*)d_in[17];

    float *X;
    uint32_t *XNf, *Wf;
    uint16_t *Qb;
    cudaGetSymbolAddress((void**)&X,   g_X);
    cudaGetSymbolAddress((void**)&XNf, g_XNf);
    cudaGetSymbolAddress((void**)&Qb,  g_Q);
    cudaGetSymbolAddress((void**)&Wf,  g_Wfrag);

    cudaFuncSetAttribute(attn_kernel, cudaFuncAttributeMaxDynamicSharedMemorySize, ATT_BYTES);
    cudaFuncSetAttribute(ff_kernel,   cudaFuncAttributeMaxDynamicSharedMemorySize, FF_BYTES);
    cudaFuncSetAttribute(tgemm<64,64,false,true,true,1,0,true,false>,
                         cudaFuncAttributeMaxDynamicSharedMemorySize, 32768);

    mean_kernel<<<32, 256>>>(hsi, lidar);
    dfm_kernel<<<16, 256>>>(fmg_w);
    build_kernel<<<(M2*DIMC + 255)/256, 256>>>(hsi, cls_hsi, cls_lidar, pos_hsi, pos_lidar);
    ln_frag_kernel<<<M2/8, 256>>>(X, ln1_g, ln1_b);

    prep_qv<<<DEPTH*32768/256, 256>>>(qkv_w);
    prep_gen<<<DEPTH*512*64/256, 256>>>(out_w, 512, 64, OFF_PROJ, DEPTH*512*64);
    prep_gen<<<DEPTH*64*256/256, 256>>>(ff_w1, 64, 256, OFF_FF1, DEPTH*64*256);
    prep_w2bf<<<DEPTH*8192/256, 256>>>(ff_w2);

    for (int phase = 0; phase < 2; phase++) {
        for (int L = 0; L < DEPTH; L++) {
            const uint32_t* WL = Wf + (size_t)L*PERL;
            int Ln = (L + 1) & 3;
            attn_kernel<<<1024, 512, ATT_BYTES>>>(WL + OFF_QV);
            tgemm<64,64,false,true,true,1,0,true,false><<<dim3(1,452), 256, 32768>>>(
                Qb, WL + OFF_PROJ, out_b + L*64, X,
                ln2_g + L*64, ln2_b + L*64, 512, 512, 64, 64);
            ff_kernel<<<226, 512, FF_BYTES>>>(
                XNf, WL + OFF_FF1, WL + OFF_FF2,
                ff_b1 + L*256, ff_b2 + L*64, X,
                ln1_g + Ln*64, ln1_b + Ln*64);
        }
        if (phase == 0) swap_cls_kernel<<<16, 256>>>();
    }
    final_kernel<<<16, 256>>>((float*)d_out);
}

// round 15
// speedup vs baseline: 1.6822x; 1.2442x over previous
#include <cuda_runtime.h>
#include <cuda_bf16.h>
#include <math.h>
#include <cstdint>

#define BATCH   64
#define DIMC    64
#define HEADS   8
#define DHEAD   64
#define INNER   512
#define MLPD    256
#define DEPTH   4
#define NPATCH  225
#define NTOK    226
#define M2      (2*BATCH*NTOK)   /* 28928 rows */
#define EPSV    1e-5f
#define SCALEV  0.125f

/* ---------------- mma helpers ---------------- */
__device__ __forceinline__ uint32_t smem_u32(const void* p) {
    uint32_t a;
    asm("{ .reg .u64 t; cvta.to.shared.u64 t, %1; cvt.u32.u64 %0, t; }" : "=r"(a) : "l"(p));
    return a;
}
__device__ __forceinline__ void mma_bf16(float* c, const uint32_t* a, const uint32_t* b) {
    asm volatile("mma.sync.aligned.m16n8k16.row.col.f32.bf16.bf16.f32 "
        "{%0,%1,%2,%3}, {%4,%5,%6,%7}, {%8,%9}, {%0,%1,%2,%3};"
        : "+f"(c[0]), "+f"(c[1]), "+f"(c[2]), "+f"(c[3])
        : "r"(a[0]), "r"(a[1]), "r"(a[2]), "r"(a[3]), "r"(b[0]), "r"(b[1]));
}
__device__ __forceinline__ void ldm_x4_trans(uint32_t* r, uint32_t addr) {
    asm volatile("ldmatrix.sync.aligned.m8n8.x4.trans.shared.b16 {%0,%1,%2,%3}, [%4];"
        : "=r"(r[0]), "=r"(r[1]), "=r"(r[2]), "=r"(r[3]) : "r"(addr));
}
#define PACKBF(r, lo_, hi_) asm("cvt.rn.bf16x2.f32 %0, %1, %2;" : "=r"(r) : "f"(hi_), "f"(lo_))
#define GELU1(x) (0.5f*(x)*(1.0f + erff((x)*0.70710678118654752f)))

/* ---------------- scratch ---------------- */
__device__ float    g_X  [(size_t)M2*DIMC];
__device__ uint16_t g_XNh[(size_t)M2*DIMC];   /* LN output, bf16 row-major */
__device__ uint16_t g_Q [(size_t)M2*INNER];   /* attn O output (bf16)      */
__device__ float    g_sdfm[BATCH*DIMC];
__device__ float    g_xmean[BATCH*2*DIMC];
/* per layer (bf16-frag words): QV 32768 @0, proj 16384 @32768,
   ff1 8192 @49152, ff2 8192 @57344 */
#define PERL     65536
#define OFF_QV   0
#define OFF_PROJ 32768
#define OFF_FF1  49152
#define OFF_FF2  57344
__device__ uint32_t g_Wfrag[(size_t)DEPTH*PERL];

/* ---------------- prologue ---------------- */
__global__ void mean_kernel(const float* __restrict__ hsi, const float* __restrict__ lidar) {
    int idx = blockIdx.x*blockDim.x + threadIdx.x;
    if (idx >= BATCH*128) return;
    int b = idx >> 7, c = idx & 127;
    const float* src = (c < 64) ? (hsi + ((size_t)b*64 + c)*NPATCH)
                                : (lidar + ((size_t)b*64 + (c-64))*NPATCH);
    float s = 0.f;
    for (int p = 0; p < NPATCH; p++) s += src[p];
    g_xmean[idx] = s * (1.0f/NPATCH);
}

__global__ void dfm_kernel(const float* __restrict__ fmg_w) {
    int idx = blockIdx.x*blockDim.x + threadIdx.x;
    if (idx >= BATCH*64) return;
    int b = idx >> 6, d = idx & 63;
    const float* xm = g_xmean + b*128;
    const float* wc = fmg_w + d*65;
    float s = 0.f;
    for (int c = 0; c < 128; c++) s += xm[c] * wc[(size_t)c*4096];
    float sig = 1.0f/(1.0f + expf(-s));
    g_sdfm[idx] = sqrtf(sig * SCALEV);
}

__global__ void build_kernel(const float* __restrict__ hsi,
                             const float* __restrict__ cls_hsi, const float* __restrict__ cls_lidar,
                             const float* __restrict__ pos_hsi, const float* __restrict__ pos_lidar) {
    int idx = blockIdx.x*blockDim.x + threadIdx.x;
    if (idx >= M2*DIMC) return;
    int c  = idx & 63;
    int n  = (idx >> 6) % NTOK;
    int bp = idx / (NTOK*64);
    int b  = bp & 63;
    int br = bp >> 6;
    const float* cls = br ? cls_lidar : cls_hsi;
    const float* pos = br ? pos_lidar : pos_hsi;
    float v = (n == 0) ? cls[c] : hsi[((size_t)b*64 + c)*NPATCH + (n-1)];
    g_X[idx] = v + pos[n*64 + c];
}

/* ---------------- layernorm -> XNh (bf16 rows), initial only ---------------- */
__global__ void ln_h_kernel(const float* __restrict__ Xp,
                            const float* __restrict__ g, const float* __restrict__ bb) {
    int w = threadIdx.x >> 5, lane = threadIdx.x & 31;
    int row = blockIdx.x*8 + w;
    const float* xr = Xp + (size_t)row*64;
    float x0 = xr[lane], x1 = xr[lane+32];
    float s = x0 + x1;
    #pragma unroll
    for (int o = 16; o; o >>= 1) s += __shfl_xor_sync(0xffffffffu, s, o);
    float m = s * (1.0f/64.0f);
    float d0 = x0 - m, d1 = x1 - m;
    float v = d0*d0 + d1*d1;
    #pragma unroll
    for (int o = 16; o; o >>= 1) v += __shfl_xor_sync(0xffffffffu, v, o);
    float r = rsqrtf(v*(1.0f/64.0f) + EPSV);
    __nv_bfloat16 h0 = __float2bfloat16(d0*r*g[lane]    + bb[lane]);
    __nv_bfloat16 h1 = __float2bfloat16(d1*r*g[lane+32] + bb[lane+32]);
    g_XNh[(size_t)row*64 + lane]      = *(uint16_t*)&h0;
    g_XNh[(size_t)row*64 + lane + 32] = *(uint16_t*)&h1;
}

/* ---------------- weight prep (bf16 B-fragment layouts) ---------------- */
__global__ void prep_qv(const float* __restrict__ qkv_w) {
    int idx = blockIdx.x*blockDim.x + threadIdx.x;
    if (idx >= DEPTH*32768) return;
    int h_ = idx & 1;
    int l  = (idx >> 1) & 31;
    int j  = (idx >> 6) & 127;
    int kb = (idx >> 13) & 3;
    int L  = idx >> 15;
    int k = kb*16 + (l & 3)*2 + h_*8;
    int n = j*8 + (l >> 2);
    int col = (n < 512) ? n : n + 512;
    const float* wp = qkv_w + (size_t)L*64*1536;
    uint32_t pk;
    PACKBF(pk, wp[(size_t)k*1536 + col], wp[(size_t)(k+1)*1536 + col]);
    g_Wfrag[(size_t)L*PERL + OFF_QV + idx % 32768] = pk;
}
/* generic [K,N] fp32 -> bf16 frag; perw = (K/16)*(N/8)*64 words/layer */
__global__ void prep_bf(const float* __restrict__ w, int K, int N, int dstoff, int perw) {
    int idx = blockIdx.x*blockDim.x + threadIdx.x;
    if (idx >= DEPTH*perw) return;
    int L = idx / perw, rem = idx % perw;
    int h_ = rem & 1;
    int l  = (rem >> 1) & 31;
    int jk = rem >> 6;
    int j  = jk % (N >> 3), kb = jk / (N >> 3);
    int k = kb*16 + (l & 3)*2 + h_*8;
    int n = j*8 + (l >> 2);
    const float* wp = w + (size_t)L*K*N;
    uint32_t pk;
    PACKBF(pk, wp[(size_t)k*N + n], wp[(size_t)(k+1)*N + n]);
    g_Wfrag[(size_t)L*PERL + dstoff + rem] = pk;
}

/* ---------------- fused proj+LN2+FF1+FF2+LN1 ----------------
   512 threads (16 warps, 4m x 4n), 128 rows/CTA, grid 226.
   smem: Xs 18432B (proj A tile / XN2 bf16), rowbuf 33792B (fp32 X'),
   Hsm 67584B. All weights via __ldg from bf16-frag global (L1-hot). */
#define PF_XS    0
#define PF_RB    18432
#define PF_H     52224
#define PF_BYTES 119808
#define XS       72
#define HSTR     264

__global__ void __launch_bounds__(512) pff_kernel(
    const uint32_t* __restrict__ Wp, const uint32_t* __restrict__ W1f,
    const uint32_t* __restrict__ W2f,
    const float* __restrict__ bp, const float* __restrict__ b1, const float* __restrict__ b2,
    float* __restrict__ Xp,
    const float* __restrict__ ln2g, const float* __restrict__ ln2b,
    const float* __restrict__ ln1g, const float* __restrict__ ln1b)
{
    extern __shared__ char smc[];
    uint16_t* Xs = (uint16_t*)(smc + PF_XS);
    float* rowbuf = (float*)(smc + PF_RB);     /* stride 66 */
    uint16_t* Hsm = (uint16_t*)(smc + PF_H);

    int t = threadIdx.x, lane = t & 31, w = t >> 5;
    int wm = w & 3, wn = w >> 2;
    int m0 = blockIdx.x * 128;
    int r = lane >> 2, c2 = (lane & 3)*2;

    /* ---- proj: [128 x 64] = O[128x512]bf16 @ Wp ---- */
    float accp[2][2][4];
    #pragma unroll
    for (int i = 0; i < 2; i++)
        #pragma unroll
        for (int j = 0; j < 2; j++)
            #pragma unroll
            for (int q = 0; q < 4; q++) accp[i][j][q] = 0.f;

    for (int kt = 0; kt < 512; kt += 64) {
        if (kt) __syncthreads();
        #pragma unroll
        for (int it = 0; it < 2; it++) {
            int idx = t + it*512;
            int m = idx >> 3, k8 = (idx & 7)*8;
            *(uint4*)&Xs[m*XS + k8] = *(const uint4*)(g_Q + (size_t)(m0+m)*INNER + kt + k8);
        }
        __syncthreads();
        #pragma unroll
        for (int kb = 0; kb < 4; kb++) {
            int kbg = (kt >> 4) + kb;
            uint32_t af[2][4];
            #pragma unroll
            for (int mf = 0; mf < 2; mf++) {
                const uint16_t* xr = Xs + (wm*32 + mf*16 + r)*XS + kb*16 + c2;
                af[mf][0] = *(const uint32_t*)(xr);
                af[mf][1] = *(const uint32_t*)(xr + 8*XS);
                af[mf][2] = *(const uint32_t*)(xr + 8);
                af[mf][3] = *(const uint32_t*)(xr + 8*XS + 8);
            }
            #pragma unroll
            for (int nj = 0; nj < 2; nj++) {
                int j = wn*2 + nj;
                uint2 bw = __ldg((const uint2*)(Wp + (size_t)((kbg*8 + j)*32 + lane)*2));
                #pragma unroll
                for (int mf = 0; mf < 2; mf++)
                    mma_bf16(accp[mf][nj], af[mf], (const uint32_t*)&bw);
            }
        }
    }
    __syncthreads();

    /* proj epilogue: + bias + X residual -> rowbuf (X') */
    #pragma unroll
    for (int mf = 0; mf < 2; mf++) {
        int ml = wm*32 + mf*16 + r;
        #pragma unroll
        for (int nj = 0; nj < 2; nj++) {
            int nout = wn*16 + nj*8 + c2;
            float2 bb = *(const float2*)&bp[nout];
            float2 o0 = *(const float2*)(Xp + (size_t)(m0+ml)*64 + nout);
            float2 o1 = *(const float2*)(Xp + (size_t)(m0+ml+8)*64 + nout);
            rowbuf[ml*66 + nout]       = accp[mf][nj][0] + bb.x + o0.x;
            rowbuf[ml*66 + nout + 1]   = accp[mf][nj][1] + bb.y + o0.y;
            rowbuf[(ml+8)*66 + nout]   = accp[mf][nj][2] + bb.x + o1.x;
            rowbuf[(ml+8)*66 + nout+1] = accp[mf][nj][3] + bb.y + o1.y;
        }
    }
    __syncthreads();

    /* LN2 -> XN2 bf16 in Xs */
    {
        float lg0 = ln2g[lane], lg1 = ln2g[lane+32];
        float lb0 = ln2b[lane], lb1 = ln2b[lane+32];
        #pragma unroll 1
        for (int i = 0; i < 8; i++) {
            int rr = w*8 + i;
            float x0 = rowbuf[rr*66 + lane], x1 = rowbuf[rr*66 + lane + 32];
            float s = x0 + x1;
            #pragma unroll
            for (int o = 16; o; o >>= 1) s += __shfl_xor_sync(0xffffffffu, s, o);
            float mean = s * (1.0f/64.0f);
            float d0 = x0 - mean, d1 = x1 - mean;
            float vv = d0*d0 + d1*d1;
            #pragma unroll
            for (int o = 16; o; o >>= 1) vv += __shfl_xor_sync(0xffffffffu, vv, o);
            float ri = rsqrtf(vv*(1.0f/64.0f) + EPSV);
            __nv_bfloat16 h0 = __float2bfloat16(d0*ri*lg0 + lb0);
            __nv_bfloat16 h1 = __float2bfloat16(d1*ri*lg1 + lb1);
            Xs[rr*XS + lane]      = *(uint16_t*)&h0;
            Xs[rr*XS + lane + 32] = *(uint16_t*)&h1;
        }
    }
    __syncthreads();

    /* ---- FF1: [128 x 256] = XN2[128x64] @ W1, bf16, GELU -> Hsm ---- */
    {
        float acc1[2][8][4];
        #pragma unroll
        for (int i = 0; i < 2; i++)
            #pragma unroll
            for (int j = 0; j < 8; j++)
                #pragma unroll
                for (int q = 0; q < 4; q++) acc1[i][j][q] = 0.f;
        #pragma unroll
        for (int kb = 0; kb < 4; kb++) {
            uint32_t af[2][4];
            #pragma unroll
            for (int mf = 0; mf < 2; mf++) {
                const uint16_t* xr = Xs + (wm*32 + mf*16 + r)*XS + kb*16 + c2;
                af[mf][0] = *(const uint32_t*)(xr);
                af[mf][1] = *(const uint32_t*)(xr + 8*XS);
                af[mf][2] = *(const uint32_t*)(xr + 8);
                af[mf][3] = *(const uint32_t*)(xr + 8*XS + 8);
            }
            #pragma unroll
            for (int nj = 0; nj < 8; nj++) {
                int j = wn*8 + nj;
                uint2 bw = __ldg((const uint2*)(W1f + (size_t)((kb*32 + j)*32 + lane)*2));
                #pragma unroll
                for (int mf = 0; mf < 2; mf++)
                    mma_bf16(acc1[mf][nj], af[mf], (const uint32_t*)&bw);
            }
        }
        #pragma unroll
        for (int mf = 0; mf < 2; mf++) {
            int row0 = wm*32 + mf*16 + r;
            #pragma unroll
            for (int nj = 0; nj < 8; nj++) {
                int col = wn*64 + nj*8 + c2;
                float2 bb = *(const float2*)&b1[col];
                float v00 = GELU1(acc1[mf][nj][0] + bb.x);
                float v01 = GELU1(acc1[mf][nj][1] + bb.y);
                float v10 = GELU1(acc1[mf][nj][2] + bb.x);
                float v11 = GELU1(acc1[mf][nj][3] + bb.y);
                uint32_t pk0, pk1;
                PACKBF(pk0, v00, v01);
                PACKBF(pk1, v10, v11);
                *(uint32_t*)&Hsm[row0*HSTR + col]       = pk0;
                *(uint32_t*)&Hsm[(row0 + 8)*HSTR + col] = pk1;
            }
        }
    }
    __syncthreads();

    /* ---- FF2: [128 x 64] = H[128x256] @ W2, bf16 ---- */
    float acc2[2][2][4];
    #pragma unroll
    for (int i = 0; i < 2; i++)
        #pragma unroll
        for (int j = 0; j < 2; j++)
            #pragma unroll
            for (int q = 0; q < 4; q++) acc2[i][j][q] = 0.f;
    #pragma unroll
    for (int kb = 0; kb < 16; kb++) {
        uint32_t af[2][4];
        #pragma unroll
        for (int mf = 0; mf < 2; mf++) {
            const uint16_t* hrow = Hsm + (wm*32 + mf*16 + r)*HSTR + kb*16 + c2;
            af[mf][0] = *(const uint32_t*)(hrow);
            af[mf][1] = *(const uint32_t*)(hrow + 8*HSTR);
            af[mf][2] = *(const uint32_t*)(hrow + 8);
            af[mf][3] = *(const uint32_t*)(hrow + 8*HSTR + 8);
        }
        #pragma unroll
        for (int nj = 0; nj < 2; nj++) {
            int j = wn*2 + nj;
            uint2 bw = __ldg((const uint2*)(W2f + (size_t)((kb*8 + j)*32 + lane)*2));
            #pragma unroll
            for (int mf = 0; mf < 2; mf++)
                mma_bf16(acc2[mf][nj], af[mf], (const uint32_t*)&bw);
        }
    }

    /* FF2 epilogue: + b2 + X' residual -> g_X (single write) + rowbuf */
    #pragma unroll
    for (int mf = 0; mf < 2; mf++) {
        int ml = wm*32 + mf*16 + r;
        int mrow = m0 + ml;
        #pragma unroll
        for (int nj = 0; nj < 2; nj++) {
            int nout = wn*16 + nj*8 + c2;
            float2 bb = *(const float2*)&b2[nout];
            float v00 = acc2[mf][nj][0] + bb.x + rowbuf[ml*66 + nout];
            float v01 = acc2[mf][nj][1] + bb.y + rowbuf[ml*66 + nout + 1];
            float v10 = acc2[mf][nj][2] + bb.x + rowbuf[(ml+8)*66 + nout];
            float v11 = acc2[mf][nj][3] + bb.y + rowbuf[(ml+8)*66 + nout + 1];
            float2 s0; s0.x = v00; s0.y = v01;
            float2 s1; s1.x = v10; s1.y = v11;
            *(float2*)(Xp + (size_t)mrow*64 + nout)     = s0;
            *(float2*)(Xp + (size_t)(mrow+8)*64 + nout) = s1;
            rowbuf[ml*66 + nout]       = v00;
            rowbuf[ml*66 + nout + 1]   = v01;
            rowbuf[(ml+8)*66 + nout]   = v10;
            rowbuf[(ml+8)*66 + nout+1] = v11;
        }
    }
    __syncthreads();

    /* LN1(next layer) -> g_XNh */
    {
        float lg0 = ln1g[lane], lg1 = ln1g[lane+32];
        float lb0 = ln1b[lane], lb1 = ln1b[lane+32];
        #pragma unroll 1
        for (int i = 0; i < 8; i++) {
            int rr = w*8 + i;
            float x0 = rowbuf[rr*66 + lane], x1 = rowbuf[rr*66 + lane + 32];
            float s = x0 + x1;
            #pragma unroll
            for (int o = 16; o; o >>= 1) s += __shfl_xor_sync(0xffffffffu, s, o);
            float mean = s * (1.0f/64.0f);
            float d0 = x0 - mean, d1 = x1 - mean;
            float vv = d0*d0 + d1*d1;
            #pragma unroll
            for (int o = 16; o; o >>= 1) vv += __shfl_xor_sync(0xffffffffu, vv, o);
            float ri = rsqrtf(vv*(1.0f/64.0f) + EPSV);
            int m = m0 + rr;
            __nv_bfloat16 h0 = __float2bfloat16(d0*ri*lg0 + lb0);
            __nv_bfloat16 h1 = __float2bfloat16(d1*ri*lg1 + lb1);
            g_XNh[(size_t)m*64 + lane]      = *(uint16_t*)&h0;
            g_XNh[(size_t)m*64 + lane + 32] = *(uint16_t*)&h1;
        }
    }
}

/* ---------------- fused QV + attention (unchanged from R13/14) ---------------- */
#define XSTRIDE 72
#define XBUF    36864
#define ATT_BYTES (3*XBUF)

__global__ void __launch_bounds__(512) attn_kernel(const uint32_t* __restrict__ Wqv) {
    extern __shared__ char smc[];
    uint16_t* Xh = (uint16_t*)smc;
    uint16_t* Qh = (uint16_t*)(smc + XBUF);
    uint16_t* Vh = (uint16_t*)(smc + 2*XBUF);
    uint32_t vbase = smem_u32(smc) + 2*XBUF;

    int t = threadIdx.x;
    int bh = blockIdx.x;
    int bp = bh >> 3, h = bh & 7;
    int bidx = bp & 63;
    uint16_t* Ob = g_Q + (size_t)bp*NTOK*INNER + h*DHEAD;
    const uint16_t* Xg = g_XNh + (size_t)bp*NTOK*64;

    for (int f = t; f < NTOK*8; f += 512) {
        int n = f >> 3, d8 = (f & 7)*8;
        *(uint4*)&Xh[n*XSTRIDE + d8] = *(const uint4*)(Xg + (size_t)n*64 + d8);
    }
    if (t < 270) ((uint4*)(Xh + NTOK*XSTRIDE))[t] = make_uint4(0,0,0,0);
    __syncthreads();

    int lane = t & 31, wid = t >> 5;
    int m0 = wid*16, r = lane >> 2, c2 = (lane & 3)*2;

    {
        uint32_t xa[4][4];
        #pragma unroll
        for (int kb = 0; kb < 4; kb++) {
            const uint16_t* xrow = Xh + (m0 + r)*XSTRIDE + kb*16 + c2;
            xa[kb][0] = *(const uint32_t*)(xrow);
            xa[kb][1] = *(const uint32_t*)(xrow + 8*XSTRIDE);
            xa[kb][2] = *(const uint32_t*)(xrow + 8);
            xa[kb][3] = *(const uint32_t*)(xrow + 8*XSTRIDE + 8);
        }
        float qc[8][4];
        #pragma unroll
        for (int j = 0; j < 8; j++)
            #pragma unroll
            for (int q = 0; q < 4; q++) qc[j][q] = 0.f;
        #pragma unroll
        for (int kb = 0; kb < 4; kb++)
            #pragma unroll
            for (int j = 0; j < 8; j++) {
                uint2 bw = __ldg((const uint2*)(Wqv + (size_t)(((kb*128) + h*8 + j)*32 + lane)*2));
                mma_bf16(qc[j], xa[kb], (const uint32_t*)&bw);
            }
        #pragma unroll
        for (int j = 0; j < 8; j++) {
            int d = j*8 + c2;
            float2 sd = *(const float2*)&g_sdfm[bidx*64 + d];
            uint32_t p0, p1;
            PACKBF(p0, qc[j][0]*sd.x, qc[j][1]*sd.y);
            PACKBF(p1, qc[j][2]*sd.x, qc[j][3]*sd.y);
            *(uint32_t*)&Qh[(m0 + r)*XSTRIDE + d]     = p0;
            *(uint32_t*)&Qh[(m0 + r + 8)*XSTRIDE + d] = p1;
        }
        float vc[8][4];
        #pragma unroll
        for (int j = 0; j < 8; j++)
            #pragma unroll
            for (int q = 0; q < 4; q++) vc[j][q] = 0.f;
        #pragma unroll
        for (int kb = 0; kb < 4; kb++)
            #pragma unroll
            for (int j = 0; j < 8; j++) {
                uint2 bw = __ldg((const uint2*)(Wqv + (size_t)(((kb*128) + 64 + h*8 + j)*32 + lane)*2));
                mma_bf16(vc[j], xa[kb], (const uint32_t*)&bw);
            }
        #pragma unroll
        for (int j = 0; j < 8; j++) {
            int d = j*8 + c2;
            uint32_t p0, p1;
            PACKBF(p0, vc[j][0], vc[j][1]);
            PACKBF(p1, vc[j][2], vc[j][3]);
            *(uint32_t*)&Vh[(m0 + r)*XSTRIDE + d]     = p0;
            *(uint32_t*)&Vh[(m0 + r + 8)*XSTRIDE + d] = p1;
        }
    }
    __syncthreads();

    uint32_t qa[4][4];
    #pragma unroll
    for (int kb = 0; kb < 4; kb++) {
        const uint16_t* qrow = Qh + (m0 + r)*XSTRIDE + kb*16 + c2;
        qa[kb][0] = *(const uint32_t*)(qrow);
        qa[kb][1] = *(const uint32_t*)(qrow + 8*XSTRIDE);
        qa[kb][2] = *(const uint32_t*)(qrow + 8);
        qa[kb][3] = *(const uint32_t*)(qrow + 8*XSTRIDE + 8);
    }

    float O[8][4];
    #pragma unroll
    for (int nt = 0; nt < 8; nt++)
        #pragma unroll
        for (int j = 0; j < 4; j++) O[nt][j] = 0.f;
    float rs0 = 0.f, rs1 = 0.f;

    for (int ch = 0; ch < 4; ch++) {
        float S[8][4];
        #pragma unroll
        for (int nt = 0; nt < 8; nt++)
            #pragma unroll
            for (int j = 0; j < 4; j++) S[nt][j] = 0.f;
        #pragma unroll
        for (int kb = 0; kb < 4; kb++) {
            #pragma unroll
            for (int nt = 0; nt < 8; nt++) {
                const uint16_t* brow = Qh + (ch*64 + nt*8 + r)*XSTRIDE + kb*16 + c2;
                uint32_t b[2] = { *(const uint32_t*)brow, *(const uint32_t*)(brow + 8) };
                mma_bf16(S[nt], qa[kb], b);
            }
        }
        uint32_t pa[4][4];
        #pragma unroll
        for (int nt = 0; nt < 8; nt++) {
            int col = ch*64 + nt*8 + c2;
            float e0 = (col     < NTOK) ? __expf(S[nt][0]) : 0.f;
            float e1 = (col + 1 < NTOK) ? __expf(S[nt][1]) : 0.f;
            float e2 = (col     < NTOK) ? __expf(S[nt][2]) : 0.f;
            float e3 = (col + 1 < NTOK) ? __expf(S[nt][3]) : 0.f;
            rs0 += e0 + e1;
            rs1 += e2 + e3;
            uint32_t plo, phi;
            PACKBF(plo, e0, e1);
            PACKBF(phi, e2, e3);
            pa[nt >> 1][(nt & 1)*2]     = plo;
            pa[nt >> 1][(nt & 1)*2 + 1] = phi;
        }
        #pragma unroll
        for (int kb = 0; kb < 4; kb++) {
            uint32_t vb[16];
            int krow = ch*64 + kb*16 + (lane & 15);
            int coff = 8*(lane >> 4);
            #pragma unroll
            for (int q = 0; q < 4; q++)
                ldm_x4_trans(vb + q*4, vbase + (uint32_t)(krow*XSTRIDE + q*16 + coff)*2);
            #pragma unroll
            for (int nt = 0; nt < 8; nt++)
                mma_bf16(O[nt], pa[kb], &vb[(nt >> 1)*4 + (nt & 1)*2]);
        }
    }

    #pragma unroll
    for (int o = 1; o <= 2; o <<= 1) {
        rs0 += __shfl_xor_sync(0xffffffffu, rs0, o);
        rs1 += __shfl_xor_sync(0xffffffffu, rs1, o);
    }
    float ri0 = 1.0f/rs0, ri1 = 1.0f/rs1;
    int i0 = m0 + r;
    if (i0 < NTOK) {
        uint16_t* op = Ob + (size_t)i0*INNER;
        #pragma unroll
        for (int nt = 0; nt < 8; nt++) {
            uint32_t pk;
            PACKBF(pk, O[nt][0]*ri0, O[nt][1]*ri0);
            *(uint32_t*)(op + nt*8 + c2) = pk;
        }
    }
    if (i0 + 8 < NTOK) {
        uint16_t* op = Ob + (size_t)(i0 + 8)*INNER;
        #pragma unroll
        for (int nt = 0; nt < 8; nt++) {
            uint32_t pk;
            PACKBF(pk, O[nt][2]*ri1, O[nt][3]*ri1);
            *(uint32_t*)(op + nt*8 + c2) = pk;
        }
    }
}

/* ---------------- token exchange (X + XNh) + final ---------------- */
__global__ void swap_cls_kernel() {
    int idx = blockIdx.x*blockDim.x + threadIdx.x;
    if (idx >= BATCH*64) return;
    int b = idx >> 6, c = idx & 63;
    size_t i0 = (size_t)(b*NTOK)*64 + c;
    size_t i1 = (size_t)((b+BATCH)*NTOK)*64 + c;
    float a = g_X[i0], d = g_X[i1];
    g_X[i0] = d; g_X[i1] = a;
    uint16_t p = g_XNh[i0], q = g_XNh[i1];
    g_XNh[i0] = q; g_XNh[i1] = p;
}

__global__ void final_kernel(float* __restrict__ out) {
    int idx = blockIdx.x*blockDim.x + threadIdx.x;
    if (idx >= BATCH*64) return;
    int b = idx >> 6, c = idx & 63;
    out[idx] = g_X[(size_t)b*NTOK*64 + c] + g_X[(size_t)(b+BATCH)*NTOK*64 + c];
}

/* ---------------- host ---------------- */
extern "C" void kernel_launch(void* const* d_in, const int* in_sizes, int n_in,
                              void* d_out, int out_size)
{
    const float* hsi       = (const float*)d_in[0];
    const float* lidar     = (const float*)d_in[1];
    const float* cls_hsi   = (const float*)d_in[2];
    const float* cls_lidar = (const float*)d_in[3];
    const float* pos_hsi   = (const float*)d_in[4];
    const float* pos_lidar = (const float*)d_in[5];
    const float* fmg_w     = (const float*)d_in[6];
    const float* ln1_g     = (const float*)d_in[7];
    const float* ln1_b     = (const float*)d_in[8];
    const float* qkv_w     = (const float*)d_in[9];
    const float* out_w     = (const float*)d_in[10];
    const float* out_b     = (const float*)d_in[11];
    const float* ln2_g     = (const float*)d_in[12];
    const float* ln2_b     = (const float*)d_in[13];
    const float* ff_w1     = (const float*)d_in[14];
    const float* ff_b1     = (const float*)d_in[15];
    const float* ff_w2     = (const float*)d_in[16];
    const float* ff_b2     = (const float*)d_in[17];

    float *X;
    uint32_t *Wf;
    cudaGetSymbolAddress((void**)&X,  g_X);
    cudaGetSymbolAddress((void**)&Wf, g_Wfrag);

    cudaFuncSetAttribute(attn_kernel, cudaFuncAttributeMaxDynamicSharedMemorySize, ATT_BYTES);
    cudaFuncSetAttribute(pff_kernel,  cudaFuncAttributeMaxDynamicSharedMemorySize, PF_BYTES);

    mean_kernel<<<32, 256>>>(hsi, lidar);
    dfm_kernel<<<16, 256>>>(fmg_w);
    build_kernel<<<(M2*DIMC + 255)/256, 256>>>(hsi, cls_hsi, cls_lidar, pos_hsi, pos_lidar);
    ln_h_kernel<<<M2/8, 256>>>(X, ln1_g, ln1_b);

    prep_qv<<<DEPTH*32768/256, 256>>>(qkv_w);
    prep_bf<<<DEPTH*16384/256, 256>>>(out_w, 512, 64, OFF_PROJ, 16384);
    prep_bf<<<DEPTH*8192/256, 256>>>(ff_w1, 64, 256, OFF_FF1, 8192);
    prep_bf<<<DEPTH*8192/256, 256>>>(ff_w2, 256, 64, OFF_FF2, 8192);

    for (int phase = 0; phase < 2; phase++) {
        for (int L = 0; L < DEPTH; L++) {
            const uint32_t* WL = Wf + (size_t)L*PERL;
            int Ln = (L + 1) & 3;
            attn_kernel<<<1024, 512, ATT_BYTES>>>(WL + OFF_QV);
            pff_kernel<<<226, 512, PF_BYTES>>>(
                WL + OFF_PROJ, WL + OFF_FF1, WL + OFF_FF2,
                out_b + L*64, ff_b1 + L*256, ff_b2 + L*64, X,
                ln2_g + L*64, ln2_b + L*64,
                ln1_g + Ln*64, ln1_b + Ln*64);
        }
        if (phase == 0) swap_cls_kernel<<<16, 256>>>();
    }
    final_kernel<<<16, 256>>>((float*)d_out);
}

// round 16
// speedup vs baseline: 1.9206x; 1.1417x over previous
#include <cuda_runtime.h>
#include <cuda_bf16.h>
#include <math.h>
#include <cstdint>

#define BATCH   64
#define DIMC    64
#define HEADS   8
#define DHEAD   64
#define INNER   512
#define MLPD    256
#define DEPTH   4
#define NPATCH  225
#define NTOK    226
#define M2      (2*BATCH*NTOK)   /* 28928 rows */
#define EPSV    1e-5f
#define SCALEV  0.125f

/* ---------------- mma helpers ---------------- */
__device__ __forceinline__ uint32_t smem_u32(const void* p) {
    uint32_t a;
    asm("{ .reg .u64 t; cvta.to.shared.u64 t, %1; cvt.u32.u64 %0, t; }" : "=r"(a) : "l"(p));
    return a;
}
__device__ __forceinline__ void mma_bf16(float* c, const uint32_t* a, const uint32_t* b) {
    asm volatile("mma.sync.aligned.m16n8k16.row.col.f32.bf16.bf16.f32 "
        "{%0,%1,%2,%3}, {%4,%5,%6,%7}, {%8,%9}, {%0,%1,%2,%3};"
        : "+f"(c[0]), "+f"(c[1]), "+f"(c[2]), "+f"(c[3])
        : "r"(a[0]), "r"(a[1]), "r"(a[2]), "r"(a[3]), "r"(b[0]), "r"(b[1]));
}
__device__ __forceinline__ void ldm_x4_trans(uint32_t* r, uint32_t addr) {
    asm volatile("ldmatrix.sync.aligned.m8n8.x4.trans.shared.b16 {%0,%1,%2,%3}, [%4];"
        : "=r"(r[0]), "=r"(r[1]), "=r"(r[2]), "=r"(r[3]) : "r"(addr));
}
#define PACKBF(r, lo_, hi_) asm("cvt.rn.bf16x2.f32 %0, %1, %2;" : "=r"(r) : "f"(hi_), "f"(lo_))
#define GELU1(x) (0.5f*(x)*(1.0f + erff((x)*0.70710678118654752f)))
__device__ __forceinline__ float bf2f(uint16_t h) {
    return __uint_as_float(((uint32_t)h) << 16);
}

/* ---------------- scratch ---------------- */
__device__ float    g_X  [(size_t)M2*DIMC];
__device__ uint16_t g_XNh[(size_t)M2*DIMC];   /* LN output, bf16 row-major */
__device__ uint16_t g_Q [(size_t)M2*INNER];   /* attn O output (bf16)      */
__device__ float    g_sdfm[BATCH*DIMC];
__device__ float    g_xmean[BATCH*2*DIMC];
/* per layer (bf16-frag words): QV 32768 @0, proj 16384 @32768,
   ff1 8192 @49152, ff2 8192 @57344 */
#define PERL     65536
#define OFF_QV   0
#define OFF_PROJ 32768
#define OFF_FF1  49152
#define OFF_FF2  57344
__device__ uint32_t g_Wfrag[(size_t)DEPTH*PERL];

/* ---------------- prologue ---------------- */
__global__ void mean_kernel(const float* __restrict__ hsi, const float* __restrict__ lidar) {
    int idx = blockIdx.x*blockDim.x + threadIdx.x;
    if (idx >= BATCH*128) return;
    int b = idx >> 7, c = idx & 127;
    const float* src = (c < 64) ? (hsi + ((size_t)b*64 + c)*NPATCH)
                                : (lidar + ((size_t)b*64 + (c-64))*NPATCH);
    float s = 0.f;
    for (int p = 0; p < NPATCH; p++) s += src[p];
    g_xmean[idx] = s * (1.0f/NPATCH);
}

__global__ void dfm_kernel(const float* __restrict__ fmg_w) {
    int idx = blockIdx.x*blockDim.x + threadIdx.x;
    if (idx >= BATCH*64) return;
    int b = idx >> 6, d = idx & 63;
    const float* xm = g_xmean + b*128;
    const float* wc = fmg_w + d*65;
    float s = 0.f;
    for (int c = 0; c < 128; c++) s += xm[c] * wc[(size_t)c*4096];
    float sig = 1.0f/(1.0f + expf(-s));
    g_sdfm[idx] = sqrtf(sig * SCALEV);
}

__global__ void build_kernel(const float* __restrict__ hsi,
                             const float* __restrict__ cls_hsi, const float* __restrict__ cls_lidar,
                             const float* __restrict__ pos_hsi, const float* __restrict__ pos_lidar) {
    int idx = blockIdx.x*blockDim.x + threadIdx.x;
    if (idx >= M2*DIMC) return;
    int c  = idx & 63;
    int n  = (idx >> 6) % NTOK;
    int bp = idx / (NTOK*64);
    int b  = bp & 63;
    int br = bp >> 6;
    const float* cls = br ? cls_lidar : cls_hsi;
    const float* pos = br ? pos_lidar : pos_hsi;
    float v = (n == 0) ? cls[c] : hsi[((size_t)b*64 + c)*NPATCH + (n-1)];
    g_X[idx] = v + pos[n*64 + c];
}

/* ---------------- layernorm -> XNh (bf16 rows), initial only ---------------- */
__global__ void ln_h_kernel(const float* __restrict__ Xp,
                            const float* __restrict__ g, const float* __restrict__ bb) {
    int w = threadIdx.x >> 5, lane = threadIdx.x & 31;
    int row = blockIdx.x*8 + w;
    const float* xr = Xp + (size_t)row*64;
    float x0 = xr[lane], x1 = xr[lane+32];
    float s = x0 + x1;
    #pragma unroll
    for (int o = 16; o; o >>= 1) s += __shfl_xor_sync(0xffffffffu, s, o);
    float m = s * (1.0f/64.0f);
    float d0 = x0 - m, d1 = x1 - m;
    float v = d0*d0 + d1*d1;
    #pragma unroll
    for (int o = 16; o; o >>= 1) v += __shfl_xor_sync(0xffffffffu, v, o);
    float r = rsqrtf(v*(1.0f/64.0f) + EPSV);
    __nv_bfloat16 h0 = __float2bfloat16(d0*r*g[lane]    + bb[lane]);
    __nv_bfloat16 h1 = __float2bfloat16(d1*r*g[lane+32] + bb[lane+32]);
    g_XNh[(size_t)row*64 + lane]      = *(uint16_t*)&h0;
    g_XNh[(size_t)row*64 + lane + 32] = *(uint16_t*)&h1;
}

/* ---------------- weight prep (bf16 B-fragment layouts) ---------------- */
__global__ void prep_qv(const float* __restrict__ qkv_w) {
    int idx = blockIdx.x*blockDim.x + threadIdx.x;
    if (idx >= DEPTH*32768) return;
    int h_ = idx & 1;
    int l  = (idx >> 1) & 31;
    int j  = (idx >> 6) & 127;
    int kb = (idx >> 13) & 3;
    int L  = idx >> 15;
    int k = kb*16 + (l & 3)*2 + h_*8;
    int n = j*8 + (l >> 2);
    int col = (n < 512) ? n : n + 512;
    const float* wp = qkv_w + (size_t)L*64*1536;
    uint32_t pk;
    PACKBF(pk, wp[(size_t)k*1536 + col], wp[(size_t)(k+1)*1536 + col]);
    g_Wfrag[(size_t)L*PERL + OFF_QV + idx % 32768] = pk;
}
__global__ void prep_bf(const float* __restrict__ w, int K, int N, int dstoff, int perw) {
    int idx = blockIdx.x*blockDim.x + threadIdx.x;
    if (idx >= DEPTH*perw) return;
    int L = idx / perw, rem = idx % perw;
    int h_ = rem & 1;
    int l  = (rem >> 1) & 31;
    int jk = rem >> 6;
    int j  = jk % (N >> 3), kb = jk / (N >> 3);
    int k = kb*16 + (l & 3)*2 + h_*8;
    int n = j*8 + (l >> 2);
    const float* wp = w + (size_t)L*K*N;
    uint32_t pk;
    PACKBF(pk, wp[(size_t)k*N + n], wp[(size_t)(k+1)*N + n]);
    g_Wfrag[(size_t)L*PERL + dstoff + rem] = pk;
}

/* ---------------- fused proj+LN2+FF1+FF2+LN1, 64-row tiles ----------------
   256 threads (8 warps: 4m x 2n), 64 rows/CTA, grid 452, ~52KB smem, 3 CTA/SM.
   X' residual lives in fp32 registers; rowbuf is bf16 (LN inputs only). */
#define XS       72
#define PF_XS    0            /*  9216B: proj A tile / XN2 bf16 */
#define PF_RB    9216         /*  9216B: bf16 rowbuf stride 72  */
#define PF_H     18432        /* 33792B: H bf16 64 x 264        */
#define PF_BYTES 52224
#define HSTR     264

__global__ void __launch_bounds__(256, 3) pff_kernel(
    const uint32_t* __restrict__ Wp, const uint32_t* __restrict__ W1f,
    const uint32_t* __restrict__ W2f,
    const float* __restrict__ bp, const float* __restrict__ b1, const float* __restrict__ b2,
    float* __restrict__ Xp,
    const float* __restrict__ ln2g, const float* __restrict__ ln2b,
    const float* __restrict__ ln1g, const float* __restrict__ ln1b)
{
    extern __shared__ char smc[];
    uint16_t* Xs  = (uint16_t*)(smc + PF_XS);
    uint16_t* RB  = (uint16_t*)(smc + PF_RB);
    uint16_t* Hsm = (uint16_t*)(smc + PF_H);

    int t = threadIdx.x, lane = t & 31, w = t >> 5;
    int wm = w & 3, wn = w >> 2;          /* wn in {0,1} */
    int m0 = blockIdx.x * 64;
    int r = lane >> 2, c2 = (lane & 3)*2;
    int ml = wm*16 + r;

    /* ---- proj: [64 x 64] = O[64x512]bf16 @ Wp ---- */
    float xres[4][4];                      /* becomes X' fp32 after epilogue */
    #pragma unroll
    for (int j = 0; j < 4; j++)
        #pragma unroll
        for (int q = 0; q < 4; q++) xres[j][q] = 0.f;

    for (int kt = 0; kt < 512; kt += 64) {
        if (kt) __syncthreads();
        #pragma unroll
        for (int it = 0; it < 2; it++) {
            int idx = t + it*256;
            int m = idx >> 3, k8 = (idx & 7)*8;
            *(uint4*)&Xs[m*XS + k8] = *(const uint4*)(g_Q + (size_t)(m0+m)*INNER + kt + k8);
        }
        __syncthreads();
        #pragma unroll
        for (int kb = 0; kb < 4; kb++) {
            int kbg = (kt >> 4) + kb;
            uint32_t af[4];
            const uint16_t* xr = Xs + ml*XS + kb*16 + c2;
            af[0] = *(const uint32_t*)(xr);
            af[1] = *(const uint32_t*)(xr + 8*XS);
            af[2] = *(const uint32_t*)(xr + 8);
            af[3] = *(const uint32_t*)(xr + 8*XS + 8);
            #pragma unroll
            for (int nj = 0; nj < 4; nj++) {
                int j = wn*4 + nj;
                uint2 bw = __ldg((const uint2*)(Wp + (size_t)((kbg*8 + j)*32 + lane)*2));
                mma_bf16(xres[nj], af, (const uint32_t*)&bw);
            }
        }
    }
    __syncthreads();

    /* proj epilogue: X' = acc + bias + X(global) -> xres regs + RB bf16 */
    #pragma unroll
    for (int nj = 0; nj < 4; nj++) {
        int nout = wn*32 + nj*8 + c2;
        float2 bb = *(const float2*)&bp[nout];
        float2 o0 = *(const float2*)(Xp + (size_t)(m0+ml)*64 + nout);
        float2 o1 = *(const float2*)(Xp + (size_t)(m0+ml+8)*64 + nout);
        xres[nj][0] += bb.x + o0.x;
        xres[nj][1] += bb.y + o0.y;
        xres[nj][2] += bb.x + o1.x;
        xres[nj][3] += bb.y + o1.y;
        uint32_t pk0, pk1;
        PACKBF(pk0, xres[nj][0], xres[nj][1]);
        PACKBF(pk1, xres[nj][2], xres[nj][3]);
        *(uint32_t*)&RB[ml*XS + nout]       = pk0;
        *(uint32_t*)&RB[(ml+8)*XS + nout]   = pk1;
    }
    __syncthreads();

    /* LN2 (bf16 inputs) -> XN2 bf16 in Xs */
    {
        float lg0 = ln2g[lane], lg1 = ln2g[lane+32];
        float lb0 = ln2b[lane], lb1 = ln2b[lane+32];
        #pragma unroll 1
        for (int i = 0; i < 8; i++) {
            int rr = w*8 + i;
            float x0 = bf2f(RB[rr*XS + lane]), x1 = bf2f(RB[rr*XS + lane + 32]);
            float s = x0 + x1;
            #pragma unroll
            for (int o = 16; o; o >>= 1) s += __shfl_xor_sync(0xffffffffu, s, o);
            float mean = s * (1.0f/64.0f);
            float d0 = x0 - mean, d1 = x1 - mean;
            float vv = d0*d0 + d1*d1;
            #pragma unroll
            for (int o = 16; o; o >>= 1) vv += __shfl_xor_sync(0xffffffffu, vv, o);
            float ri = rsqrtf(vv*(1.0f/64.0f) + EPSV);
            __nv_bfloat16 h0 = __float2bfloat16(d0*ri*lg0 + lb0);
            __nv_bfloat16 h1 = __float2bfloat16(d1*ri*lg1 + lb1);
            Xs[rr*XS + lane]      = *(uint16_t*)&h0;
            Xs[rr*XS + lane + 32] = *(uint16_t*)&h1;
        }
    }
    __syncthreads();

    /* ---- FF1: [64 x 256] bf16, two sequential N-halves, GELU -> Hsm ---- */
    #pragma unroll 1
    for (int half = 0; half < 2; half++) {
        float acc1[8][4];
        #pragma unroll
        for (int j = 0; j < 8; j++)
            #pragma unroll
            for (int q = 0; q < 4; q++) acc1[j][q] = 0.f;
        #pragma unroll
        for (int kb = 0; kb < 4; kb++) {
            uint32_t af[4];
            const uint16_t* xr = Xs + ml*XS + kb*16 + c2;
            af[0] = *(const uint32_t*)(xr);
            af[1] = *(const uint32_t*)(xr + 8*XS);
            af[2] = *(const uint32_t*)(xr + 8);
            af[3] = *(const uint32_t*)(xr + 8*XS + 8);
            #pragma unroll
            for (int nj = 0; nj < 8; nj++) {
                int j = half*16 + wn*8 + nj;
                uint2 bw = __ldg((const uint2*)(W1f + (size_t)((kb*32 + j)*32 + lane)*2));
                mma_bf16(acc1[nj], af, (const uint32_t*)&bw);
            }
        }
        #pragma unroll
        for (int nj = 0; nj < 8; nj++) {
            int col = half*128 + wn*64 + nj*8 + c2;
            float2 bb = *(const float2*)&b1[col];
            float v00 = GELU1(acc1[nj][0] + bb.x);
            float v01 = GELU1(acc1[nj][1] + bb.y);
            float v10 = GELU1(acc1[nj][2] + bb.x);
            float v11 = GELU1(acc1[nj][3] + bb.y);
            uint32_t pk0, pk1;
            PACKBF(pk0, v00, v01);
            PACKBF(pk1, v10, v11);
            *(uint32_t*)&Hsm[ml*HSTR + col]       = pk0;
            *(uint32_t*)&Hsm[(ml + 8)*HSTR + col] = pk1;
        }
    }
    __syncthreads();

    /* ---- FF2: [64 x 64] = H[64x256] @ W2, bf16 ---- */
    float acc2[4][4];
    #pragma unroll
    for (int j = 0; j < 4; j++)
        #pragma unroll
        for (int q = 0; q < 4; q++) acc2[j][q] = 0.f;
    #pragma unroll
    for (int kb = 0; kb < 16; kb++) {
        uint32_t af[4];
        const uint16_t* hrow = Hsm + ml*HSTR + kb*16 + c2;
        af[0] = *(const uint32_t*)(hrow);
        af[1] = *(const uint32_t*)(hrow + 8*HSTR);
        af[2] = *(const uint32_t*)(hrow + 8);
        af[3] = *(const uint32_t*)(hrow + 8*HSTR + 8);
        #pragma unroll
        for (int nj = 0; nj < 4; nj++) {
            int j = wn*4 + nj;
            uint2 bw = __ldg((const uint2*)(W2f + (size_t)((kb*8 + j)*32 + lane)*2));
            mma_bf16(acc2[nj], af, (const uint32_t*)&bw);
        }
    }

    /* FF2 epilogue: final = acc2 + b2 + X'(regs) -> g_X fp32 (single write) + RB bf16 */
    #pragma unroll
    for (int nj = 0; nj < 4; nj++) {
        int nout = wn*32 + nj*8 + c2;
        float2 bb = *(const float2*)&b2[nout];
        float v00 = acc2[nj][0] + bb.x + xres[nj][0];
        float v01 = acc2[nj][1] + bb.y + xres[nj][1];
        float v10 = acc2[nj][2] + bb.x + xres[nj][2];
        float v11 = acc2[nj][3] + bb.y + xres[nj][3];
        float2 s0; s0.x = v00; s0.y = v01;
        float2 s1; s1.x = v10; s1.y = v11;
        *(float2*)(Xp + (size_t)(m0+ml)*64 + nout)   = s0;
        *(float2*)(Xp + (size_t)(m0+ml+8)*64 + nout) = s1;
        uint32_t pk0, pk1;
        PACKBF(pk0, v00, v01);
        PACKBF(pk1, v10, v11);
        *(uint32_t*)&RB[ml*XS + nout]     = pk0;
        *(uint32_t*)&RB[(ml+8)*XS + nout] = pk1;
    }
    __syncthreads();

    /* LN1(next layer) -> g_XNh */
    {
        float lg0 = ln1g[lane], lg1 = ln1g[lane+32];
        float lb0 = ln1b[lane], lb1 = ln1b[lane+32];
        #pragma unroll 1
        for (int i = 0; i < 8; i++) {
            int rr = w*8 + i;
            float x0 = bf2f(RB[rr*XS + lane]), x1 = bf2f(RB[rr*XS + lane + 32]);
            float s = x0 + x1;
            #pragma unroll
            for (int o = 16; o; o >>= 1) s += __shfl_xor_sync(0xffffffffu, s, o);
            float mean = s * (1.0f/64.0f);
            float d0 = x0 - mean, d1 = x1 - mean;
            float vv = d0*d0 + d1*d1;
            #pragma unroll
            for (int o = 16; o; o >>= 1) vv += __shfl_xor_sync(0xffffffffu, vv, o);
            float ri = rsqrtf(vv*(1.0f/64.0f) + EPSV);
            int m = m0 + rr;
            __nv_bfloat16 h0 = __float2bfloat16(d0*ri*lg0 + lb0);
            __nv_bfloat16 h1 = __float2bfloat16(d1*ri*lg1 + lb1);
            g_XNh[(size_t)m*64 + lane]      = *(uint16_t*)&h0;
            g_XNh[(size_t)m*64 + lane + 32] = *(uint16_t*)&h1;
        }
    }
}

/* ---------------- fused QV + attention (unchanged from R13-15) ---------------- */
#define XSTRIDE 72
#define XBUF    36864
#define ATT_BYTES (3*XBUF)

__global__ void __launch_bounds__(512) attn_kernel(const uint32_t* __restrict__ Wqv) {
    extern __shared__ char smc[];
    uint16_t* Xh = (uint16_t*)smc;
    uint16_t* Qh = (uint16_t*)(smc + XBUF);
    uint16_t* Vh = (uint16_t*)(smc + 2*XBUF);
    uint32_t vbase = smem_u32(smc) + 2*XBUF;

    int t = threadIdx.x;
    int bh = blockIdx.x;
    int bp = bh >> 3, h = bh & 7;
    int bidx = bp & 63;
    uint16_t* Ob = g_Q + (size_t)bp*NTOK*INNER + h*DHEAD;
    const uint16_t* Xg = g_XNh + (size_t)bp*NTOK*64;

    for (int f = t; f < NTOK*8; f += 512) {
        int n = f >> 3, d8 = (f & 7)*8;
        *(uint4*)&Xh[n*XSTRIDE + d8] = *(const uint4*)(Xg + (size_t)n*64 + d8);
    }
    if (t < 270) ((uint4*)(Xh + NTOK*XSTRIDE))[t] = make_uint4(0,0,0,0);
    __syncthreads();

    int lane = t & 31, wid = t >> 5;
    int m0 = wid*16, r = lane >> 2, c2 = (lane & 3)*2;

    {
        uint32_t xa[4][4];
        #pragma unroll
        for (int kb = 0; kb < 4; kb++) {
            const uint16_t* xrow = Xh + (m0 + r)*XSTRIDE + kb*16 + c2;
            xa[kb][0] = *(const uint32_t*)(xrow);
            xa[kb][1] = *(const uint32_t*)(xrow + 8*XSTRIDE);
            xa[kb][2] = *(const uint32_t*)(xrow + 8);
            xa[kb][3] = *(const uint32_t*)(xrow + 8*XSTRIDE + 8);
        }
        float qc[8][4];
        #pragma unroll
        for (int j = 0; j < 8; j++)
            #pragma unroll
            for (int q = 0; q < 4; q++) qc[j][q] = 0.f;
        #pragma unroll
        for (int kb = 0; kb < 4; kb++)
            #pragma unroll
            for (int j = 0; j < 8; j++) {
                uint2 bw = __ldg((const uint2*)(Wqv + (size_t)(((kb*128) + h*8 + j)*32 + lane)*2));
                mma_bf16(qc[j], xa[kb], (const uint32_t*)&bw);
            }
        #pragma unroll
        for (int j = 0; j < 8; j++) {
            int d = j*8 + c2;
            float2 sd = *(const float2*)&g_sdfm[bidx*64 + d];
            uint32_t p0, p1;
            PACKBF(p0, qc[j][0]*sd.x, qc[j][1]*sd.y);
            PACKBF(p1, qc[j][2]*sd.x, qc[j][3]*sd.y);
            *(uint32_t*)&Qh[(m0 + r)*XSTRIDE + d]     = p0;
            *(uint32_t*)&Qh[(m0 + r + 8)*XSTRIDE + d] = p1;
        }
        float vc[8][4];
        #pragma unroll
        for (int j = 0; j < 8; j++)
            #pragma unroll
            for (int q = 0; q < 4; q++) vc[j][q] = 0.f;
        #pragma unroll
        for (int kb = 0; kb < 4; kb++)
            #pragma unroll
            for (int j = 0; j < 8; j++) {
                uint2 bw = __ldg((const uint2*)(Wqv + (size_t)(((kb*128) + 64 + h*8 + j)*32 + lane)*2));
                mma_bf16(vc[j], xa[kb], (const uint32_t*)&bw);
            }
        #pragma unroll
        for (int j = 0; j < 8; j++) {
            int d = j*8 + c2;
            uint32_t p0, p1;
            PACKBF(p0, vc[j][0], vc[j][1]);
            PACKBF(p1, vc[j][2], vc[j][3]);
            *(uint32_t*)&Vh[(m0 + r)*XSTRIDE + d]     = p0;
            *(uint32_t*)&Vh[(m0 + r + 8)*XSTRIDE + d] = p1;
        }
    }
    __syncthreads();

    uint32_t qa[4][4];
    #pragma unroll
    for (int kb = 0; kb < 4; kb++) {
        const uint16_t* qrow = Qh + (m0 + r)*XSTRIDE + kb*16 + c2;
        qa[kb][0] = *(const uint32_t*)(qrow);
        qa[kb][1] = *(const uint32_t*)(qrow + 8*XSTRIDE);
        qa[kb][2] = *(const uint32_t*)(qrow + 8);
        qa[kb][3] = *(const uint32_t*)(qrow + 8*XSTRIDE + 8);
    }

    float O[8][4];
    #pragma unroll
    for (int nt = 0; nt < 8; nt++)
        #pragma unroll
        for (int j = 0; j < 4; j++) O[nt][j] = 0.f;
    float rs0 = 0.f, rs1 = 0.f;

    for (int ch = 0; ch < 4; ch++) {
        float S[8][4];
        #pragma unroll
        for (int nt = 0; nt < 8; nt++)
            #pragma unroll
            for (int j = 0; j < 4; j++) S[nt][j] = 0.f;
        #pragma unroll
        for (int kb = 0; kb < 4; kb++) {
            #pragma unroll
            for (int nt = 0; nt < 8; nt++) {
                const uint16_t* brow = Qh + (ch*64 + nt*8 + r)*XSTRIDE + kb*16 + c2;
                uint32_t b[2] = { *(const uint32_t*)brow, *(const uint32_t*)(brow + 8) };
                mma_bf16(S[nt], qa[kb], b);
            }
        }
        uint32_t pa[4][4];
        #pragma unroll
        for (int nt = 0; nt < 8; nt++) {
            int col = ch*64 + nt*8 + c2;
            float e0 = (col     < NTOK) ? __expf(S[nt][0]) : 0.f;
            float e1 = (col + 1 < NTOK) ? __expf(S[nt][1]) : 0.f;
            float e2 = (col     < NTOK) ? __expf(S[nt][2]) : 0.f;
            float e3 = (col + 1 < NTOK) ? __expf(S[nt][3]) : 0.f;
            rs0 += e0 + e1;
            rs1 += e2 + e3;
            uint32_t plo, phi;
            PACKBF(plo, e0, e1);
            PACKBF(phi, e2, e3);
            pa[nt >> 1][(nt & 1)*2]     = plo;
            pa[nt >> 1][(nt & 1)*2 + 1] = phi;
        }
        #pragma unroll
        for (int kb = 0; kb < 4; kb++) {
            uint32_t vb[16];
            int krow = ch*64 + kb*16 + (lane & 15);
            int coff = 8*(lane >> 4);
            #pragma unroll
            for (int q = 0; q < 4; q++)
                ldm_x4_trans(vb + q*4, vbase + (uint32_t)(krow*XSTRIDE + q*16 + coff)*2);
            #pragma unroll
            for (int nt = 0; nt < 8; nt++)
                mma_bf16(O[nt], pa[kb], &vb[(nt >> 1)*4 + (nt & 1)*2]);
        }
    }

    #pragma unroll
    for (int o = 1; o <= 2; o <<= 1) {
        rs0 += __shfl_xor_sync(0xffffffffu, rs0, o);
        rs1 += __shfl_xor_sync(0xffffffffu, rs1, o);
    }
    float ri0 = 1.0f/rs0, ri1 = 1.0f/rs1;
    int i0 = m0 + r;
    if (i0 < NTOK) {
        uint16_t* op = Ob + (size_t)i0*INNER;
        #pragma unroll
        for (int nt = 0; nt < 8; nt++) {
            uint32_t pk;
            PACKBF(pk, O[nt][0]*ri0, O[nt][1]*ri0);
            *(uint32_t*)(op + nt*8 + c2) = pk;
        }
    }
    if (i0 + 8 < NTOK) {
        uint16_t* op = Ob + (size_t)(i0 + 8)*INNER;
        #pragma unroll
        for (int nt = 0; nt < 8; nt++) {
            uint32_t pk;
            PACKBF(pk, O[nt][2]*ri1, O[nt][3]*ri1);
            *(uint32_t*)(op + nt*8 + c2) = pk;
        }
    }
}

/* ---------------- token exchange (X + XNh) + final ---------------- */
__global__ void swap_cls_kernel() {
    int idx = blockIdx.x*blockDim.x + threadIdx.x;
    if (idx >= BATCH*64) return;
    int b = idx >> 6, c = idx & 63;
    size_t i0 = (size_t)(b*NTOK)*64 + c;
    size_t i1 = (size_t)((b+BATCH)*NTOK)*64 + c;
    float a = g_X[i0], d = g_X[i1];
    g_X[i0] = d; g_X[i1] = a;
    uint16_t p = g_XNh[i0], q = g_XNh[i1];
    g_XNh[i0] = q; g_XNh[i1] = p;
}

__global__ void final_kernel(float* __restrict__ out) {
    int idx = blockIdx.x*blockDim.x + threadIdx.x;
    if (idx >= BATCH*64) return;
    int b = idx >> 6, c = idx & 63;
    out[idx] = g_X[(size_t)b*NTOK*64 + c] + g_X[(size_t)(b+BATCH)*NTOK*64 + c];
}

/* ---------------- host ---------------- */
extern "C" void kernel_launch(void* const* d_in, const int* in_sizes, int n_in,
                              void* d_out, int out_size)
{
    const float* hsi       = (const float*)d_in[0];
    const float* lidar     = (const float*)d_in[1];
    const float* cls_hsi   = (const float*)d_in[2];
    const float* cls_lidar = (const float*)d_in[3];
    const float* pos_hsi   = (const float*)d_in[4];
    const float* pos_lidar = (const float*)d_in[5];
    const float* fmg_w     = (const float*)d_in[6];
    const float* ln1_g     = (const float*)d_in[7];
    const float* ln1_b     = (const float*)d_in[8];
    const float* qkv_w     = (const float*)d_in[9];
    const float* out_w     = (const float*)d_in[10];
    const float* out_b     = (const float*)d_in[11];
    const float* ln2_g     = (const float*)d_in[12];
    const float* ln2_b     = (const float*)d_in[13];
    const float* ff_w1     = (const float*)d_in[14];
    const float* ff_b1     = (const float*)d_in[15];
    const float* ff_w2     = (const float*)d_in[16];
    const float* ff_b2     = (const float*)d_in[17];

    float *X;
    uint32_t *Wf;
    cudaGetSymbolAddress((void**)&X,  g_X);
    cudaGetSymbolAddress((void**)&Wf, g_Wfrag);

    cudaFuncSetAttribute(attn_kernel, cudaFuncAttributeMaxDynamicSharedMemorySize, ATT_BYTES);
    cudaFuncSetAttribute(pff_kernel,  cudaFuncAttributeMaxDynamicSharedMemorySize, PF_BYTES);

    mean_kernel<<<32, 256>>>(hsi, lidar);
    dfm_kernel<<<16, 256>>>(fmg_w);
    build_kernel<<<(M2*DIMC + 255)/256, 256>>>(hsi, cls_hsi, cls_lidar, pos_hsi, pos_lidar);
    ln_h_kernel<<<M2/8, 256>>>(X, ln1_g, ln1_b);

    prep_qv<<<DEPTH*32768/256, 256>>>(qkv_w);
    prep_bf<<<DEPTH*16384/256, 256>>>(out_w, 512, 64, OFF_PROJ, 16384);
    prep_bf<<<DEPTH*8192/256, 256>>>(ff_w1, 64, 256, OFF_FF1, 8192);
    prep_bf<<<DEPTH*8192/256, 256>>>(ff_w2, 256, 64, OFF_FF2, 8192);

    for (int phase = 0; phase < 2; phase++) {
        for (int L = 0; L < DEPTH; L++) {
            const uint32_t* WL = Wf + (size_t)L*PERL;
            int Ln = (L + 1) & 3;
            attn_kernel<<<1024, 512, ATT_BYTES>>>(WL + OFF_QV);
            pff_kernel<<<452, 256, PF_BYTES>>>(
                WL + OFF_PROJ, WL + OFF_FF1, WL + OFF_FF2,
                out_b + L*64, ff_b1 + L*256, ff_b2 + L*64, X,
                ln2_g + L*64, ln2_b + L*64,
                ln1_g + Ln*64, ln1_b + Ln*64);
        }
        if (phase == 0) swap_cls_kernel<<<16, 256>>>();
    }
    final_kernel<<<16, 256>>>((float*)d_out);
}

// round 17
// speedup vs baseline: 1.9940x; 1.0382x over previous
#include <cuda_runtime.h>
#include <cuda_bf16.h>
#include <math.h>
#include <cstdint>

#define BATCH   64
#define DIMC    64
#define HEADS   8
#define DHEAD   64
#define INNER   512
#define MLPD    256
#define DEPTH   4
#define NPATCH  225
#define NTOK    226
#define M2      (2*BATCH*NTOK)   /* 28928 rows */
#define EPSV    1e-5f
#define SCALEV  0.125f

/* ---------------- mma helpers ---------------- */
__device__ __forceinline__ uint32_t smem_u32(const void* p) {
    uint32_t a;
    asm("{ .reg .u64 t; cvta.to.shared.u64 t, %1; cvt.u32.u64 %0, t; }" : "=r"(a) : "l"(p));
    return a;
}
__device__ __forceinline__ void mma_bf16(float* c, const uint32_t* a, const uint32_t* b) {
    asm volatile("mma.sync.aligned.m16n8k16.row.col.f32.bf16.bf16.f32 "
        "{%0,%1,%2,%3}, {%4,%5,%6,%7}, {%8,%9}, {%0,%1,%2,%3};"
        : "+f"(c[0]), "+f"(c[1]), "+f"(c[2]), "+f"(c[3])
        : "r"(a[0]), "r"(a[1]), "r"(a[2]), "r"(a[3]), "r"(b[0]), "r"(b[1]));
}
__device__ __forceinline__ void ldm_x4(uint32_t* r, uint32_t addr) {
    asm volatile("ldmatrix.sync.aligned.m8n8.x4.shared.b16 {%0,%1,%2,%3}, [%4];"
        : "=r"(r[0]), "=r"(r[1]), "=r"(r[2]), "=r"(r[3]) : "r"(addr));
}
__device__ __forceinline__ void ldm_x4_trans(uint32_t* r, uint32_t addr) {
    asm volatile("ldmatrix.sync.aligned.m8n8.x4.trans.shared.b16 {%0,%1,%2,%3}, [%4];"
        : "=r"(r[0]), "=r"(r[1]), "=r"(r[2]), "=r"(r[3]) : "r"(addr));
}
#define PACKBF(r, lo_, hi_) asm("cvt.rn.bf16x2.f32 %0, %1, %2;" : "=r"(r) : "f"(hi_), "f"(lo_))
#define GELU1(x) (0.5f*(x)*(1.0f + erff((x)*0.70710678118654752f)))
__device__ __forceinline__ float bf2f(uint16_t h) {
    return __uint_as_float(((uint32_t)h) << 16);
}

/* ---------------- scratch ---------------- */
__device__ float    g_X  [(size_t)M2*DIMC];
__device__ uint16_t g_XNh[(size_t)M2*DIMC];   /* LN output, bf16 row-major */
__device__ uint16_t g_Q [(size_t)M2*INNER];   /* attn O output (bf16)      */
__device__ float    g_sdfm[BATCH*DIMC];
__device__ float    g_xmean[BATCH*2*DIMC];
#define PERL     65536
#define OFF_QV   0
#define OFF_PROJ 32768
#define OFF_FF1  49152
#define OFF_FF2  57344
__device__ uint32_t g_Wfrag[(size_t)DEPTH*PERL];

/* ---------------- prologue ---------------- */
__global__ void mean_kernel(const float* __restrict__ hsi, const float* __restrict__ lidar) {
    int idx = blockIdx.x*blockDim.x + threadIdx.x;
    if (idx >= BATCH*128) return;
    int b = idx >> 7, c = idx & 127;
    const float* src = (c < 64) ? (hsi + ((size_t)b*64 + c)*NPATCH)
                                : (lidar + ((size_t)b*64 + (c-64))*NPATCH);
    float s = 0.f;
    for (int p = 0; p < NPATCH; p++) s += src[p];
    g_xmean[idx] = s * (1.0f/NPATCH);
}

__global__ void dfm_kernel(const float* __restrict__ fmg_w) {
    int idx = blockIdx.x*blockDim.x + threadIdx.x;
    if (idx >= BATCH*64) return;
    int b = idx >> 6, d = idx & 63;
    const float* xm = g_xmean + b*128;
    const float* wc = fmg_w + d*65;
    float s = 0.f;
    for (int c = 0; c < 128; c++) s += xm[c] * wc[(size_t)c*4096];
    float sig = 1.0f/(1.0f + expf(-s));
    g_sdfm[idx] = sqrtf(sig * SCALEV);
}

__global__ void build_kernel(const float* __restrict__ hsi,
                             const float* __restrict__ cls_hsi, const float* __restrict__ cls_lidar,
                             const float* __restrict__ pos_hsi, const float* __restrict__ pos_lidar) {
    int idx = blockIdx.x*blockDim.x + threadIdx.x;
    if (idx >= M2*DIMC) return;
    int c  = idx & 63;
    int n  = (idx >> 6) % NTOK;
    int bp = idx / (NTOK*64);
    int b  = bp & 63;
    int br = bp >> 6;
    const float* cls = br ? cls_lidar : cls_hsi;
    const float* pos = br ? pos_lidar : pos_hsi;
    float v = (n == 0) ? cls[c] : hsi[((size_t)b*64 + c)*NPATCH + (n-1)];
    g_X[idx] = v + pos[n*64 + c];
}

/* ---------------- layernorm -> XNh (bf16 rows), initial only ---------------- */
__global__ void ln_h_kernel(const float* __restrict__ Xp,
                            const float* __restrict__ g, const float* __restrict__ bb) {
    int w = threadIdx.x >> 5, lane = threadIdx.x & 31;
    int row = blockIdx.x*8 + w;
    const float* xr = Xp + (size_t)row*64;
    float x0 = xr[lane], x1 = xr[lane+32];
    float s = x0 + x1;
    #pragma unroll
    for (int o = 16; o; o >>= 1) s += __shfl_xor_sync(0xffffffffu, s, o);
    float m = s * (1.0f/64.0f);
    float d0 = x0 - m, d1 = x1 - m;
    float v = d0*d0 + d1*d1;
    #pragma unroll
    for (int o = 16; o; o >>= 1) v += __shfl_xor_sync(0xffffffffu, v, o);
    float r = rsqrtf(v*(1.0f/64.0f) + EPSV);
    __nv_bfloat16 h0 = __float2bfloat16(d0*r*g[lane]    + bb[lane]);
    __nv_bfloat16 h1 = __float2bfloat16(d1*r*g[lane+32] + bb[lane+32]);
    g_XNh[(size_t)row*64 + lane]      = *(uint16_t*)&h0;
    g_XNh[(size_t)row*64 + lane + 32] = *(uint16_t*)&h1;
}

/* ---------------- weight prep (bf16 B-fragment layouts) ---------------- */
__global__ void prep_qv(const float* __restrict__ qkv_w) {
    int idx = blockIdx.x*blockDim.x + threadIdx.x;
    if (idx >= DEPTH*32768) return;
    int h_ = idx & 1;
    int l  = (idx >> 1) & 31;
    int j  = (idx >> 6) & 127;
    int kb = (idx >> 13) & 3;
    int L  = idx >> 15;
    int k = kb*16 + (l & 3)*2 + h_*8;
    int n = j*8 + (l >> 2);
    int col = (n < 512) ? n : n + 512;
    const float* wp = qkv_w + (size_t)L*64*1536;
    uint32_t pk;
    PACKBF(pk, wp[(size_t)k*1536 + col], wp[(size_t)(k+1)*1536 + col]);
    g_Wfrag[(size_t)L*PERL + OFF_QV + idx % 32768] = pk;
}
__global__ void prep_bf(const float* __restrict__ w, int K, int N, int dstoff, int perw) {
    int idx = blockIdx.x*blockDim.x + threadIdx.x;
    if (idx >= DEPTH*perw) return;
    int L = idx / perw, rem = idx % perw;
    int h_ = rem & 1;
    int l  = (rem >> 1) & 31;
    int jk = rem >> 6;
    int j  = jk % (N >> 3), kb = jk / (N >> 3);
    int k = kb*16 + (l & 3)*2 + h_*8;
    int n = j*8 + (l >> 2);
    const float* wp = w + (size_t)L*K*N;
    uint32_t pk;
    PACKBF(pk, wp[(size_t)k*N + n], wp[(size_t)(k+1)*N + n]);
    g_Wfrag[(size_t)L*PERL + dstoff + rem] = pk;
}

/* ---------------- fused proj+LN2+FF1+FF2+LN1, 64-row tiles (unchanged R16) ---------------- */
#define XS       72
#define PF_XS    0
#define PF_RB    9216
#define PF_H     18432
#define PF_BYTES 52224
#define HSTR     264

__global__ void __launch_bounds__(256, 3) pff_kernel(
    const uint32_t* __restrict__ Wp, const uint32_t* __restrict__ W1f,
    const uint32_t* __restrict__ W2f,
    const float* __restrict__ bp, const float* __restrict__ b1, const float* __restrict__ b2,
    float* __restrict__ Xp,
    const float* __restrict__ ln2g, const float* __restrict__ ln2b,
    const float* __restrict__ ln1g, const float* __restrict__ ln1b)
{
    extern __shared__ char smc[];
    uint16_t* Xs  = (uint16_t*)(smc + PF_XS);
    uint16_t* RB  = (uint16_t*)(smc + PF_RB);
    uint16_t* Hsm = (uint16_t*)(smc + PF_H);

    int t = threadIdx.x, lane = t & 31, w = t >> 5;
    int wm = w & 3, wn = w >> 2;
    int m0 = blockIdx.x * 64;
    int r = lane >> 2, c2 = (lane & 3)*2;
    int ml = wm*16 + r;

    float xres[4][4];
    #pragma unroll
    for (int j = 0; j < 4; j++)
        #pragma unroll
        for (int q = 0; q < 4; q++) xres[j][q] = 0.f;

    for (int kt = 0; kt < 512; kt += 64) {
        if (kt) __syncthreads();
        #pragma unroll
        for (int it = 0; it < 2; it++) {
            int idx = t + it*256;
            int m = idx >> 3, k8 = (idx & 7)*8;
            *(uint4*)&Xs[m*XS + k8] = *(const uint4*)(g_Q + (size_t)(m0+m)*INNER + kt + k8);
        }
        __syncthreads();
        #pragma unroll
        for (int kb = 0; kb < 4; kb++) {
            int kbg = (kt >> 4) + kb;
            uint32_t af[4];
            const uint16_t* xr = Xs + ml*XS + kb*16 + c2;
            af[0] = *(const uint32_t*)(xr);
            af[1] = *(const uint32_t*)(xr + 8*XS);
            af[2] = *(const uint32_t*)(xr + 8);
            af[3] = *(const uint32_t*)(xr + 8*XS + 8);
            #pragma unroll
            for (int nj = 0; nj < 4; nj++) {
                int j = wn*4 + nj;
                uint2 bw = __ldg((const uint2*)(Wp + (size_t)((kbg*8 + j)*32 + lane)*2));
                mma_bf16(xres[nj], af, (const uint32_t*)&bw);
            }
        }
    }
    __syncthreads();

    #pragma unroll
    for (int nj = 0; nj < 4; nj++) {
        int nout = wn*32 + nj*8 + c2;
        float2 bb = *(const float2*)&bp[nout];
        float2 o0 = *(const float2*)(Xp + (size_t)(m0+ml)*64 + nout);
        float2 o1 = *(const float2*)(Xp + (size_t)(m0+ml+8)*64 + nout);
        xres[nj][0] += bb.x + o0.x;
        xres[nj][1] += bb.y + o0.y;
        xres[nj][2] += bb.x + o1.x;
        xres[nj][3] += bb.y + o1.y;
        uint32_t pk0, pk1;
        PACKBF(pk0, xres[nj][0], xres[nj][1]);
        PACKBF(pk1, xres[nj][2], xres[nj][3]);
        *(uint32_t*)&RB[ml*XS + nout]       = pk0;
        *(uint32_t*)&RB[(ml+8)*XS + nout]   = pk1;
    }
    __syncthreads();

    {
        float lg0 = ln2g[lane], lg1 = ln2g[lane+32];
        float lb0 = ln2b[lane], lb1 = ln2b[lane+32];
        #pragma unroll 1
        for (int i = 0; i < 8; i++) {
            int rr = w*8 + i;
            float x0 = bf2f(RB[rr*XS + lane]), x1 = bf2f(RB[rr*XS + lane + 32]);
            float s = x0 + x1;
            #pragma unroll
            for (int o = 16; o; o >>= 1) s += __shfl_xor_sync(0xffffffffu, s, o);
            float mean = s * (1.0f/64.0f);
            float d0 = x0 - mean, d1 = x1 - mean;
            float vv = d0*d0 + d1*d1;
            #pragma unroll
            for (int o = 16; o; o >>= 1) vv += __shfl_xor_sync(0xffffffffu, vv, o);
            float ri = rsqrtf(vv*(1.0f/64.0f) + EPSV);
            __nv_bfloat16 h0 = __float2bfloat16(d0*ri*lg0 + lb0);
            __nv_bfloat16 h1 = __float2bfloat16(d1*ri*lg1 + lb1);
            Xs[rr*XS + lane]      = *(uint16_t*)&h0;
            Xs[rr*XS + lane + 32] = *(uint16_t*)&h1;
        }
    }
    __syncthreads();

    #pragma unroll 1
    for (int half = 0; half < 2; half++) {
        float acc1[8][4];
        #pragma unroll
        for (int j = 0; j < 8; j++)
            #pragma unroll
            for (int q = 0; q < 4; q++) acc1[j][q] = 0.f;
        #pragma unroll
        for (int kb = 0; kb < 4; kb++) {
            uint32_t af[4];
            const uint16_t* xr = Xs + ml*XS + kb*16 + c2;
            af[0] = *(const uint32_t*)(xr);
            af[1] = *(const uint32_t*)(xr + 8*XS);
            af[2] = *(const uint32_t*)(xr + 8);
            af[3] = *(const uint32_t*)(xr + 8*XS + 8);
            #pragma unroll
            for (int nj = 0; nj < 8; nj++) {
                int j = half*16 + wn*8 + nj;
                uint2 bw = __ldg((const uint2*)(W1f + (size_t)((kb*32 + j)*32 + lane)*2));
                mma_bf16(acc1[nj], af, (const uint32_t*)&bw);
            }
        }
        #pragma unroll
        for (int nj = 0; nj < 8; nj++) {
            int col = half*128 + wn*64 + nj*8 + c2;
            float2 bb = *(const float2*)&b1[col];
            float v00 = GELU1(acc1[nj][0] + bb.x);
            float v01 = GELU1(acc1[nj][1] + bb.y);
            float v10 = GELU1(acc1[nj][2] + bb.x);
            float v11 = GELU1(acc1[nj][3] + bb.y);
            uint32_t pk0, pk1;
            PACKBF(pk0, v00, v01);
            PACKBF(pk1, v10, v11);
            *(uint32_t*)&Hsm[ml*HSTR + col]       = pk0;
            *(uint32_t*)&Hsm[(ml + 8)*HSTR + col] = pk1;
        }
    }
    __syncthreads();

    float acc2[4][4];
    #pragma unroll
    for (int j = 0; j < 4; j++)
        #pragma unroll
        for (int q = 0; q < 4; q++) acc2[j][q] = 0.f;
    #pragma unroll
    for (int kb = 0; kb < 16; kb++) {
        uint32_t af[4];
        const uint16_t* hrow = Hsm + ml*HSTR + kb*16 + c2;
        af[0] = *(const uint32_t*)(hrow);
        af[1] = *(const uint32_t*)(hrow + 8*HSTR);
        af[2] = *(const uint32_t*)(hrow + 8);
        af[3] = *(const uint32_t*)(hrow + 8*HSTR + 8);
        #pragma unroll
        for (int nj = 0; nj < 4; nj++) {
            int j = wn*4 + nj;
            uint2 bw = __ldg((const uint2*)(W2f + (size_t)((kb*8 + j)*32 + lane)*2));
            mma_bf16(acc2[nj], af, (const uint32_t*)&bw);
        }
    }

    #pragma unroll
    for (int nj = 0; nj < 4; nj++) {
        int nout = wn*32 + nj*8 + c2;
        float2 bb = *(const float2*)&b2[nout];
        float v00 = acc2[nj][0] + bb.x + xres[nj][0];
        float v01 = acc2[nj][1] + bb.y + xres[nj][1];
        float v10 = acc2[nj][2] + bb.x + xres[nj][2];
        float v11 = acc2[nj][3] + bb.y + xres[nj][3];
        float2 s0; s0.x = v00; s0.y = v01;
        float2 s1; s1.x = v10; s1.y = v11;
        *(float2*)(Xp + (size_t)(m0+ml)*64 + nout)   = s0;
        *(float2*)(Xp + (size_t)(m0+ml+8)*64 + nout) = s1;
        uint32_t pk0, pk1;
        PACKBF(pk0, v00, v01);
        PACKBF(pk1, v10, v11);
        *(uint32_t*)&RB[ml*XS + nout]     = pk0;
        *(uint32_t*)&RB[(ml+8)*XS + nout] = pk1;
    }
    __syncthreads();

    {
        float lg0 = ln1g[lane], lg1 = ln1g[lane+32];
        float lb0 = ln1b[lane], lb1 = ln1b[lane+32];
        #pragma unroll 1
        for (int i = 0; i < 8; i++) {
            int rr = w*8 + i;
            float x0 = bf2f(RB[rr*XS + lane]), x1 = bf2f(RB[rr*XS + lane + 32]);
            float s = x0 + x1;
            #pragma unroll
            for (int o = 16; o; o >>= 1) s += __shfl_xor_sync(0xffffffffu, s, o);
            float mean = s * (1.0f/64.0f);
            float d0 = x0 - mean, d1 = x1 - mean;
            float vv = d0*d0 + d1*d1;
            #pragma unroll
            for (int o = 16; o; o >>= 1) vv += __shfl_xor_sync(0xffffffffu, vv, o);
            float ri = rsqrtf(vv*(1.0f/64.0f) + EPSV);
            int m = m0 + rr;
            __nv_bfloat16 h0 = __float2bfloat16(d0*ri*lg0 + lb0);
            __nv_bfloat16 h1 = __float2bfloat16(d1*ri*lg1 + lb1);
            g_XNh[(size_t)m*64 + lane]      = *(uint16_t*)&h0;
            g_XNh[(size_t)m*64 + lane + 32] = *(uint16_t*)&h1;
        }
    }
}

/* ---------------- fused QV + attention v2 ----------------
   X buffer reused for V after QV compute; qa formed directly from qc regs;
   ldmatrix.x4 for QV A-frags and S B-frags. smem 72KB. */
#define XSTRIDE 72
#define XBUF    36864
#define ATT_BYTES (2*XBUF)

__global__ void __launch_bounds__(512) attn_kernel(const uint32_t* __restrict__ Wqv) {
    extern __shared__ char smc[];
    uint16_t* Xh = (uint16_t*)smc;            /* X rows, then V rows */
    uint16_t* Qh = (uint16_t*)(smc + XBUF);
    uint32_t xbase = smem_u32(smc);
    uint32_t qbase = xbase + XBUF;

    int t = threadIdx.x;
    int bh = blockIdx.x;
    int bp = bh >> 3, h = bh & 7;
    int bidx = bp & 63;
    uint16_t* Ob = g_Q + (size_t)bp*NTOK*INNER + h*DHEAD;
    const uint16_t* Xg = g_XNh + (size_t)bp*NTOK*64;

    for (int f = t; f < NTOK*8; f += 512) {
        int n = f >> 3, d8 = (f & 7)*8;
        *(uint4*)&Xh[n*XSTRIDE + d8] = *(const uint4*)(Xg + (size_t)n*64 + d8);
    }
    if (t < 270) ((uint4*)(Xh + NTOK*XSTRIDE))[t] = make_uint4(0,0,0,0);
    __syncthreads();

    int lane = t & 31, wid = t >> 5;
    int m0 = wid*16, r = lane >> 2, c2 = (lane & 3)*2;
    int li = lane & 7, lg = lane >> 3;          /* ldmatrix row-group decode */

    uint32_t qa[4][4];

    /* ---- QV ---- */
    {
        /* A-frags of own 16 X rows via ldmatrix.x4 */
        uint32_t xa[4][4];
        #pragma unroll
        for (int kb = 0; kb < 4; kb++) {
            int row = m0 + (lg & 1)*8 + li;
            int ko  = kb*16 + (lg >> 1)*8;
            ldm_x4(xa[kb], xbase + (uint32_t)(row*XSTRIDE + ko)*2);
        }
        /* Q */
        float qc[8][4];
        #pragma unroll
        for (int j = 0; j < 8; j++)
            #pragma unroll
            for (int q = 0; q < 4; q++) qc[j][q] = 0.f;
        #pragma unroll
        for (int kb = 0; kb < 4; kb++)
            #pragma unroll
            for (int j = 0; j < 8; j++) {
                uint2 bw = __ldg((const uint2*)(Wqv + (size_t)(((kb*128) + h*8 + j)*32 + lane)*2));
                mma_bf16(qc[j], xa[kb], (const uint32_t*)&bw);
            }
        #pragma unroll
        for (int j = 0; j < 8; j++) {
            int d = j*8 + c2;
            float2 sd = *(const float2*)&g_sdfm[bidx*64 + d];
            uint32_t p0, p1;
            PACKBF(p0, qc[j][0]*sd.x, qc[j][1]*sd.y);
            PACKBF(p1, qc[j][2]*sd.x, qc[j][3]*sd.y);
            *(uint32_t*)&Qh[(m0 + r)*XSTRIDE + d]     = p0;
            *(uint32_t*)&Qh[(m0 + r + 8)*XSTRIDE + d] = p1;
            qa[j >> 1][(j & 1)*2]     = p0;     /* A-frag direct from regs */
            qa[j >> 1][(j & 1)*2 + 1] = p1;
        }
        /* V (overwrites own X rows; xa already in regs) */
        float vc[8][4];
        #pragma unroll
        for (int j = 0; j < 8; j++)
            #pragma unroll
            for (int q = 0; q < 4; q++) vc[j][q] = 0.f;
        #pragma unroll
        for (int kb = 0; kb < 4; kb++)
            #pragma unroll
            for (int j = 0; j < 8; j++) {
                uint2 bw = __ldg((const uint2*)(Wqv + (size_t)(((kb*128) + 64 + h*8 + j)*32 + lane)*2));
                mma_bf16(vc[j], xa[kb], (const uint32_t*)&bw);
            }
        #pragma unroll
        for (int j = 0; j < 8; j++) {
            int d = j*8 + c2;
            uint32_t p0, p1;
            PACKBF(p0, vc[j][0], vc[j][1]);
            PACKBF(p1, vc[j][2], vc[j][3]);
            *(uint32_t*)&Xh[(m0 + r)*XSTRIDE + d]     = p0;
            *(uint32_t*)&Xh[(m0 + r + 8)*XSTRIDE + d] = p1;
        }
    }
    __syncthreads();

    /* ---- attention ---- */
    float O[8][4];
    #pragma unroll
    for (int nt = 0; nt < 8; nt++)
        #pragma unroll
        for (int j = 0; j < 4; j++) O[nt][j] = 0.f;
    float rs0 = 0.f, rs1 = 0.f;

    for (int ch = 0; ch < 4; ch++) {
        float S[8][4];
        #pragma unroll
        for (int nt = 0; nt < 8; nt++)
            #pragma unroll
            for (int j = 0; j < 4; j++) S[nt][j] = 0.f;
        #pragma unroll
        for (int kb = 0; kb < 4; kb++) {
            #pragma unroll
            for (int np = 0; np < 4; np++) {
                uint32_t bq[4];
                int row = ch*64 + np*16 + (lg >> 1)*8 + li;
                int ko  = kb*16 + (lg & 1)*8;
                ldm_x4(bq, qbase + (uint32_t)(row*XSTRIDE + ko)*2);
                mma_bf16(S[2*np],     qa[kb], bq);
                mma_bf16(S[2*np + 1], qa[kb], bq + 2);
            }
        }
        uint32_t pa[4][4];
        #pragma unroll
        for (int nt = 0; nt < 8; nt++) {
            int col = ch*64 + nt*8 + c2;
            float e0 = (col     < NTOK) ? __expf(S[nt][0]) : 0.f;
            float e1 = (col + 1 < NTOK) ? __expf(S[nt][1]) : 0.f;
            float e2 = (col     < NTOK) ? __expf(S[nt][2]) : 0.f;
            float e3 = (col + 1 < NTOK) ? __expf(S[nt][3]) : 0.f;
            rs0 += e0 + e1;
            rs1 += e2 + e3;
            uint32_t plo, phi;
            PACKBF(plo, e0, e1);
            PACKBF(phi, e2, e3);
            pa[nt >> 1][(nt & 1)*2]     = plo;
            pa[nt >> 1][(nt & 1)*2 + 1] = phi;
        }
        #pragma unroll
        for (int kb = 0; kb < 4; kb++) {
            uint32_t vb[16];
            int krow = ch*64 + kb*16 + (lane & 15);
            int coff = 8*(lane >> 4);
            #pragma unroll
            for (int q = 0; q < 4; q++)
                ldm_x4_trans(vb + q*4, xbase + (uint32_t)(krow*XSTRIDE + q*16 + coff)*2);
            #pragma unroll
            for (int nt = 0; nt < 8; nt++)
                mma_bf16(O[nt], pa[kb], &vb[(nt >> 1)*4 + (nt & 1)*2]);
        }
    }

    #pragma unroll
    for (int o = 1; o <= 2; o <<= 1) {
        rs0 += __shfl_xor_sync(0xffffffffu, rs0, o);
        rs1 += __shfl_xor_sync(0xffffffffu, rs1, o);
    }
    float ri0 = 1.0f/rs0, ri1 = 1.0f/rs1;
    int i0 = m0 + r;
    if (i0 < NTOK) {
        uint16_t* op = Ob + (size_t)i0*INNER;
        #pragma unroll
        for (int nt = 0; nt < 8; nt++) {
            uint32_t pk;
            PACKBF(pk, O[nt][0]*ri0, O[nt][1]*ri0);
            *(uint32_t*)(op + nt*8 + c2) = pk;
        }
    }
    if (i0 + 8 < NTOK) {
        uint16_t* op = Ob + (size_t)(i0 + 8)*INNER;
        #pragma unroll
        for (int nt = 0; nt < 8; nt++) {
            uint32_t pk;
            PACKBF(pk, O[nt][2]*ri1, O[nt][3]*ri1);
            *(uint32_t*)(op + nt*8 + c2) = pk;
        }
    }
}

/* ---------------- token exchange (X + XNh) + final ---------------- */
__global__ void swap_cls_kernel() {
    int idx = blockIdx.x*blockDim.x + threadIdx.x;
    if (idx >= BATCH*64) return;
    int b = idx >> 6, c = idx & 63;
    size_t i0 = (size_t)(b*NTOK)*64 + c;
    size_t i1 = (size_t)((b+BATCH)*NTOK)*64 + c;
    float a = g_X[i0], d = g_X[i1];
    g_X[i0] = d; g_X[i1] = a;
    uint16_t p = g_XNh[i0], q = g_XNh[i1];
    g_XNh[i0] = q; g_XNh[i1] = p;
}

__global__ void final_kernel(float* __restrict__ out) {
    int idx = blockIdx.x*blockDim.x + threadIdx.x;
    if (idx >= BATCH*64) return;
    int b = idx >> 6, c = idx & 63;
    out[idx] = g_X[(size_t)b*NTOK*64 + c] + g_X[(size_t)(b+BATCH)*NTOK*64 + c];
}

/* ---------------- host ---------------- */
extern "C" void kernel_launch(void* const* d_in, const int* in_sizes, int n_in,
                              void* d_out, int out_size)
{
    const float* hsi       = (const float*)d_in[0];
    const float* lidar     = (const float*)d_in[1];
    const float* cls_hsi   = (const float*)d_in[2];
    const float* cls_lidar = (const float*)d_in[3];
    const float* pos_hsi   = (const float*)d_in[4];
    const float* pos_lidar = (const float*)d_in[5];
    const float* fmg_w     = (const float*)d_in[6];
    const float* ln1_g     = (const float*)d_in[7];
    const float* ln1_b     = (const float*)d_in[8];
    const float* qkv_w     = (const float*)d_in[9];
    const float* out_w     = (const float*)d_in[10];
    const float* out_b     = (const float*)d_in[11];
    const float* ln2_g     = (const float*)d_in[12];
    const float* ln2_b     = (const float*)d_in[13];
    const float* ff_w1     = (const float*)d_in[14];
    const float* ff_b1     = (const float*)d_in[15];
    const float* ff_w2     = (const float*)d_in[16];
    const float* ff_b2     = (const float*)d_in[17];

    float *X;
    uint32_t *Wf;
    cudaGetSymbolAddress((void**)&X,  g_X);
    cudaGetSymbolAddress((void**)&Wf, g_Wfrag);

    cudaFuncSetAttribute(attn_kernel, cudaFuncAttributeMaxDynamicSharedMemorySize, ATT_BYTES);
    cudaFuncSetAttribute(pff_kernel,  cudaFuncAttributeMaxDynamicSharedMemorySize, PF_BYTES);

    mean_kernel<<<32, 256>>>(hsi, lidar);
    dfm_kernel<<<16, 256>>>(fmg_w);
    build_kernel<<<(M2*DIMC + 255)/256, 256>>>(hsi, cls_hsi, cls_lidar, pos_hsi, pos_lidar);
    ln_h_kernel<<<M2/8, 256>>>(X, ln1_g, ln1_b);

    prep_qv<<<DEPTH*32768/256, 256>>>(qkv_w);
    prep_bf<<<DEPTH*16384/256, 256>>>(out_w, 512, 64, OFF_PROJ, 16384);
    prep_bf<<<DEPTH*8192/256, 256>>>(ff_w1, 64, 256, OFF_FF1, 8192);
    prep_bf<<<DEPTH*8192/256, 256>>>(ff_w2, 256, 64, OFF_FF2, 8192);

    for (int phase = 0; phase < 2; phase++) {
        for (int L = 0; L < DEPTH; L++) {
            const uint32_t* WL = Wf + (size_t)L*PERL;
            int Ln = (L + 1) & 3;
            attn_kernel<<<1024, 512, ATT_BYTES>>>(WL + OFF_QV);
            pff_kernel<<<452, 256, PF_BYTES>>>(
                WL + OFF_PROJ, WL + OFF_FF1, WL + OFF_FF2,
                out_b + L*64, ff_b1 + L*256, ff_b2 + L*64, X,
                ln2_g + L*64, ln2_b + L*64,
                ln1_g + Ln*64, ln1_b + Ln*64);
        }
        if (phase == 0) swap_cls_kernel<<<16, 256>>>();
    }
    final_kernel<<<16, 256>>>((float*)d_out);
}